// round 8
// baseline (speedup 1.0000x reference)
#include <cuda_runtime.h>
#include <cuda_bf16.h>
#include <math.h>
#include <cstdint>

#define B_    2
#define C_    512
#define C3_   1536
#define H_    128
#define W_    128
#define HW_   16384
#define HEADS_ 64
#define CH_   8
#define PLANE_ (C3_ * HW_)
#define TENSOR_ ((size_t)B_ * C_ * HW_)

// ---------------- scratch ----------------
__device__ float g_conv[4][PLANE_];
__device__ float g_attn[2][B_][HEADS_][64];
__device__ float g_a[2][B_][HEADS_][64];

// ---------------- helpers ----------------
static __device__ __forceinline__ uint32_t s2u(const void* p) {
    uint32_t a;
    asm("{ .reg .u64 t; cvta.to.shared.u64 t, %1; cvt.u32.u64 %0, t; }"
        : "=r"(a) : "l"(p));
    return a;
}
static __device__ __forceinline__ void cpasync16(uint32_t dst, const void* src) {
    asm volatile("cp.async.cg.shared.global [%0], [%1], 16;" :: "r"(dst), "l"(src));
}
static __device__ __forceinline__ void cp_commit() {
    asm volatile("cp.async.commit_group;" ::: "memory");
}
template <int N>
static __device__ __forceinline__ void cp_wait() {
    asm volatile("cp.async.wait_group %0;" :: "n"(N) : "memory");
}
static __device__ __forceinline__ void mma_tf32(float& d0, float& d1, float& d2, float& d3,
                                                uint32_t a0, uint32_t a1, uint32_t a2, uint32_t a3,
                                                uint32_t b0, uint32_t b1) {
    asm volatile("mma.sync.aligned.m16n8k8.row.col.f32.tf32.tf32.f32 "
                 "{%0,%1,%2,%3}, {%4,%5,%6,%7}, {%8,%9}, {%0,%1,%2,%3};"
                 : "+f"(d0), "+f"(d1), "+f"(d2), "+f"(d3)
                 : "r"(a0), "r"(a1), "r"(a2), "r"(a3), "r"(b0), "r"(b1));
}

// ---------------- K1: tf32 mma.sync GEMM, 3-stage cp.async pipeline ----
#define BK_    16
#define APAD_  20
#define XPAD_  136
#define KITERS (C_ / BK_)   // 32
#define ST_    3
#define A_FLOATS (128 * APAD_)
#define X_FLOATS (BK_ * XPAD_)
#define GEMM_SMEM ((ST_ * (A_FLOATS + X_FLOATS)) * 4)   // 56832 B

__global__ __launch_bounds__(256, 2) void k_gemm_mma(
    const float* __restrict__ hsi, const float* __restrict__ lidar,
    const float* __restrict__ hw_w, const float* __restrict__ hw_b,
    const float* __restrict__ lw_w, const float* __restrict__ lw_b,
    int m_off)
{
    extern __shared__ float smem_g[];
    float* Asm = smem_g;
    float* Xsm = smem_g + ST_ * A_FLOATS;

    const int tid  = threadIdx.x;
    const int lane = tid & 31;
    const int wid  = tid >> 5;
    const int g    = lane >> 2;
    const int c    = lane & 3;

    const int mb  = blockIdx.z;
    const int mod = mb >> 1, bb = mb & 1;
    const float* Wm   = mod ? lw_w : hw_w;
    const float* bias = mod ? lw_b : hw_b;
    const float* X = (mod ? lidar : hsi) + (size_t)bb * C_ * HW_;
    float* Y = g_conv[mb];
    const int m0 = (blockIdx.x + m_off) * 128;
    const int n0 = blockIdx.y * 128;

    const int warp_m = (wid & 1) * 64;
    const int warp_n = (wid >> 1) * 32;

    const int a_row0 = tid >> 2;
    const int a_gr   = tid & 3;

    const uint32_t asb = s2u(Asm);
    const uint32_t xsb = s2u(Xsm);

    float acc[4][4][4] = {};

    auto load_stage = [&](int s, int k0) {
        #pragma unroll
        for (int i = 0; i < 2; i++) {
            int row = a_row0 + 64 * i;
            cpasync16(asb + (s * A_FLOATS + row * APAD_ + a_gr * 4) * 4,
                      &Wm[(size_t)(m0 + row) * C_ + k0 + a_gr * 4]);
        }
        #pragma unroll
        for (int i = 0; i < 2; i++) {
            int idx = tid + 256 * i;
            int kk  = idx >> 5;
            int gr  = idx & 31;
            cpasync16(xsb + (s * X_FLOATS + kk * XPAD_ + gr * 4) * 4,
                      &X[(size_t)(k0 + kk) * HW_ + n0 + gr * 4]);
        }
    };

    load_stage(0, 0);
    cp_commit();
    load_stage(1, BK_);
    cp_commit();

    for (int it = 0; it < KITERS; it++) {
        const int s = it % ST_;
        cp_wait<1>();
        __syncthreads();

        const float* Ap = &Asm[s * A_FLOATS];
        const float* Xp = &Xsm[s * X_FLOATS];
        #pragma unroll
        for (int ks = 0; ks < BK_; ks += 8) {
            uint32_t af[4][4], bf[4][2];
            #pragma unroll
            for (int i = 0; i < 4; i++) {
                int row = warp_m + 16 * i + g;
                af[i][0] = __float_as_uint(Ap[row * APAD_ + ks + c]);
                af[i][1] = __float_as_uint(Ap[(row + 8) * APAD_ + ks + c]);
                af[i][2] = __float_as_uint(Ap[row * APAD_ + ks + c + 4]);
                af[i][3] = __float_as_uint(Ap[(row + 8) * APAD_ + ks + c + 4]);
            }
            #pragma unroll
            for (int j = 0; j < 4; j++) {
                int col = warp_n + 8 * j + g;
                bf[j][0] = __float_as_uint(Xp[(ks + c) * XPAD_ + col]);
                bf[j][1] = __float_as_uint(Xp[(ks + c + 4) * XPAD_ + col]);
            }
            #pragma unroll
            for (int i = 0; i < 4; i++)
                #pragma unroll
                for (int j = 0; j < 4; j++)
                    mma_tf32(acc[i][j][0], acc[i][j][1], acc[i][j][2], acc[i][j][3],
                             af[i][0], af[i][1], af[i][2], af[i][3],
                             bf[j][0], bf[j][1]);
        }
        const int nxt = it + 2;
        if (nxt < KITERS) load_stage(nxt % ST_, nxt * BK_);
        cp_commit();
    }

    #pragma unroll
    for (int i = 0; i < 4; i++) {
        const int r0 = m0 + warp_m + 16 * i + g;
        const float bi0 = bias[r0];
        const float bi1 = bias[r0 + 8];
        #pragma unroll
        for (int j = 0; j < 4; j++) {
            const int col = n0 + warp_n + 8 * j + 2 * c;
            *(float2*)&Y[(size_t)r0 * HW_ + col] =
                make_float2(acc[i][j][0] + bi0, acc[i][j][1] + bi0);
            *(float2*)&Y[(size_t)(r0 + 8) * HW_ + col] =
                make_float2(acc[i][j][2] + bi1, acc[i][j][3] + bi1);
        }
    }
}

// ---------------- K3: fused dwconv(q,k) + ssq + channel-attention dot ----
__global__ __launch_bounds__(512) void k_dwattn(
    const float* __restrict__ hdww, const float* __restrict__ hdwb,
    const float* __restrict__ ldww, const float* __restrict__ ldwb,
    const float* __restrict__ temp1, const float* __restrict__ temp2)
{
    __shared__ float rowbuf[16][132];
    __shared__ float sq[16];
    __shared__ float red[4][16][4];

    const int h = blockIdx.x, bb = blockIdx.y, a = blockIdx.z;
    const int tid = threadIdx.x;
    const int w = tid >> 5, lane = tid & 31;

    const int isk = w >> 3;
    const int ch  = w & 7;
    const int mod = isk ? (1 - a) : a;
    const int plane = (isk ? C_ : 0) + h * CH_ + ch;
    const float* src = g_conv[mod * 2 + bb] + (size_t)plane * HW_;
    const float* wp  = (mod ? ldww : hdww) + plane * 9;
    float wk[9];
    #pragma unroll
    for (int t = 0; t < 9; t++) wk[t] = __ldg(&wp[t]);
    const float bias = (mod ? ldwb : hdwb)[plane];

    const int x0 = lane * 4;

    float4 pv, cv, nv;
    float pl, pr, cl, cr, nl, nr;
    auto loadrow = [&](int y, float4& v, float& l, float& r) {
        if (y < 0 || y >= H_) { v = make_float4(0.f,0.f,0.f,0.f); l = 0.f; r = 0.f; return; }
        v = *(const float4*)&src[y * W_ + x0];
        l = __shfl_up_sync(0xffffffffu, v.w, 1);
        if (lane == 0) l = 0.f;
        r = __shfl_down_sync(0xffffffffu, v.x, 1);
        if (lane == 31) r = 0.f;
    };
    pv = make_float4(0.f,0.f,0.f,0.f); pl = pr = 0.f;
    loadrow(0, cv, cl, cr);
    loadrow(1, nv, nl, nr);

    const int xq  = tid & 127;
    const int blk = tid >> 7;
    const int c0  = (blk & 1) * 4;
    const int d0  = (blk >> 1) * 4;

    float ssq = 0.f;
    float acc[4][4] = {};

    for (int y = 0; y < H_; y++) {
        float o0 = bias
            + wk[0]*pl   + wk[1]*pv.x + wk[2]*pv.y
            + wk[3]*cl   + wk[4]*cv.x + wk[5]*cv.y
            + wk[6]*nl   + wk[7]*nv.x + wk[8]*nv.y;
        float o1 = bias
            + wk[0]*pv.x + wk[1]*pv.y + wk[2]*pv.z
            + wk[3]*cv.x + wk[4]*cv.y + wk[5]*cv.z
            + wk[6]*nv.x + wk[7]*nv.y + wk[8]*nv.z;
        float o2 = bias
            + wk[0]*pv.y + wk[1]*pv.z + wk[2]*pv.w
            + wk[3]*cv.y + wk[4]*cv.z + wk[5]*cv.w
            + wk[6]*nv.y + wk[7]*nv.z + wk[8]*nv.w;
        float o3 = bias
            + wk[0]*pv.z + wk[1]*pv.w + wk[2]*pr
            + wk[3]*cv.z + wk[4]*cv.w + wk[5]*cr
            + wk[6]*nv.z + wk[7]*nv.w + wk[8]*nr;

        __syncthreads();
        *(float4*)&rowbuf[w][x0] = make_float4(o0, o1, o2, o3);
        ssq += o0*o0 + o1*o1 + o2*o2 + o3*o3;

        pv = cv; pl = cl; pr = cr;
        cv = nv; cl = nl; cr = nr;
        loadrow(y + 2, nv, nl, nr);

        __syncthreads();
        float qv[4], kv[4];
        #pragma unroll
        for (int i = 0; i < 4; i++) qv[i] = rowbuf[c0 + i][xq];
        #pragma unroll
        for (int j = 0; j < 4; j++) kv[j] = rowbuf[8 + d0 + j][xq];
        #pragma unroll
        for (int i = 0; i < 4; i++)
            #pragma unroll
            for (int j = 0; j < 4; j++)
                acc[i][j] += qv[i] * kv[j];
    }

    #pragma unroll
    for (int off = 16; off; off >>= 1)
        ssq += __shfl_down_sync(0xffffffffu, ssq, off);
    if (lane == 0) sq[w] = ssq;

    const int wsub = (tid >> 5) & 3;
    #pragma unroll
    for (int i = 0; i < 4; i++)
        #pragma unroll
        for (int j = 0; j < 4; j++) {
            float v = acc[i][j];
            #pragma unroll
            for (int off = 16; off; off >>= 1)
                v += __shfl_down_sync(0xffffffffu, v, off);
            if (lane == 0) red[blk][i * 4 + j][wsub] = v;
        }
    __syncthreads();

    if (tid < 64) {
        int cc = tid >> 3, dd = tid & 7;
        int bq = (cc >> 2) + ((dd >> 2) << 1);
        int ii = cc & 3, jj = dd & 3;
        float dot = red[bq][ii * 4 + jj][0] + red[bq][ii * 4 + jj][1]
                  + red[bq][ii * 4 + jj][2] + red[bq][ii * 4 + jj][3];
        float qn = fmaxf(sqrtf(sq[cc]), 1e-12f);
        float kn = fmaxf(sqrtf(sq[8 + dd]), 1e-12f);
        float tmp = (a == 0 ? temp1 : temp2)[h];
        g_attn[a][bb][h][tid] = dot / (qn * kn) * tmp;
    }
}

// ---------------- K4: score fusion + BN + ReLU + softmax (smem-staged) ---------
__global__ __launch_bounds__(512) void k_fuse(
    const float* __restrict__ projw, const float* __restrict__ projb,
    const float* __restrict__ gamma, const float* __restrict__ beta,
    const float* __restrict__ mean,  const float* __restrict__ var)
{
    __shared__ float attn_s[2][64][64];   // 32 KB
    const int ogrp = blockIdx.x, bb = blockIdx.y;
    const int tid = threadIdx.x;

    for (int i = tid; i < 2 * 64 * 64; i += 512) {
        int aa = i >> 12, rest = i & 4095;
        attn_s[aa][rest >> 6][rest & 63] = g_attn[aa][bb][rest >> 6][rest & 63];
    }
    __syncthreads();

    const int o  = ogrp * 8 + (tid >> 6);
    const int cd = tid & 63;
    const float* w = projw + o * 128;
    float s = __ldg(&projb[o]);
    #pragma unroll 8
    for (int i = 0; i < 64; i++) s += __ldg(&w[i])      * attn_s[0][i][cd];
    #pragma unroll 8
    for (int i = 0; i < 64; i++) s += __ldg(&w[64 + i]) * attn_s[1][i][cd];
    s = (s - __ldg(&mean[o])) * rsqrtf(__ldg(&var[o]) + 1e-5f) * __ldg(&gamma[o]) + __ldg(&beta[o]);
    s = fmaxf(s, 0.f);
    #pragma unroll
    for (int a = 0; a < 2; a++) {
        float v = s + attn_s[a][o][cd];
        float m = v;
        #pragma unroll
        for (int off = 4; off; off >>= 1)
            m = fmaxf(m, __shfl_xor_sync(0xffffffffu, m, off, 8));
        float e = expf(v - m);
        float su = e;
        #pragma unroll
        for (int off = 4; off; off >>= 1)
            su += __shfl_xor_sync(0xffffffffu, su, off, 8);
        g_a[a][bb][o][cd] = e / su;
    }
}

// ---------------- K5: fused dwconv(v) + (a @ v + v + x) -----------------------
// grid: (h=64, mb=4). 256 threads = 8 warps; warp w owns v-channel w of the head.
__global__ __launch_bounds__(256) void k_vout(
    const float* __restrict__ hsi, const float* __restrict__ lidar,
    const float* __restrict__ hdww, const float* __restrict__ hdwb,
    const float* __restrict__ ldww, const float* __restrict__ ldwb,
    float* __restrict__ out)
{
    __shared__ float rowbuf[8][132];

    const int h = blockIdx.x, mb = blockIdx.y;
    const int mod = mb >> 1, bb = mb & 1;
    const int tid = threadIdx.x;
    const int w = tid >> 5, lane = tid & 31;

    const int plane = 2 * C_ + h * CH_ + w;
    const float* src = g_conv[mb] + (size_t)plane * HW_;
    const float* wp  = (mod ? ldww : hdww) + plane * 9;
    float wk[9];
    #pragma unroll
    for (int t = 0; t < 9; t++) wk[t] = __ldg(&wp[t]);
    const float bias = (mod ? ldwb : hdwb)[plane];

    // attention row for this output channel (c = w)
    float ar[8];
    #pragma unroll
    for (int d = 0; d < 8; d++) ar[d] = __ldg(&g_a[mod][bb][h][w * 8 + d]);

    const float* xc = (mod ? lidar : hsi) + (size_t)(bb * C_ + h * CH_ + w) * HW_;
    float* oc = out + (size_t)mod * TENSOR_ + (size_t)(bb * C_ + h * CH_ + w) * HW_;

    const int x0 = lane * 4;

    float4 pv, cv, nv;
    float pl, pr, cl, cr, nl, nr;
    auto loadrow = [&](int y, float4& v, float& l, float& r) {
        if (y < 0 || y >= H_) { v = make_float4(0.f,0.f,0.f,0.f); l = 0.f; r = 0.f; return; }
        v = *(const float4*)&src[y * W_ + x0];
        l = __shfl_up_sync(0xffffffffu, v.w, 1);
        if (lane == 0) l = 0.f;
        r = __shfl_down_sync(0xffffffffu, v.x, 1);
        if (lane == 31) r = 0.f;
    };
    pv = make_float4(0.f,0.f,0.f,0.f); pl = pr = 0.f;
    loadrow(0, cv, cl, cr);
    loadrow(1, nv, nl, nr);

    for (int y = 0; y < H_; y++) {
        float o0 = bias
            + wk[0]*pl   + wk[1]*pv.x + wk[2]*pv.y
            + wk[3]*cl   + wk[4]*cv.x + wk[5]*cv.y
            + wk[6]*nl   + wk[7]*nv.x + wk[8]*nv.y;
        float o1 = bias
            + wk[0]*pv.x + wk[1]*pv.y + wk[2]*pv.z
            + wk[3]*cv.x + wk[4]*cv.y + wk[5]*cv.z
            + wk[6]*nv.x + wk[7]*nv.y + wk[8]*nv.z;
        float o2 = bias
            + wk[0]*pv.y + wk[1]*pv.z + wk[2]*pv.w
            + wk[3]*cv.y + wk[4]*cv.z + wk[5]*cv.w
            + wk[6]*nv.y + wk[7]*nv.z + wk[8]*nv.w;
        float o3 = bias
            + wk[0]*pv.z + wk[1]*pv.w + wk[2]*pr
            + wk[3]*cv.z + wk[4]*cv.w + wk[5]*cr
            + wk[6]*nv.z + wk[7]*nv.w + wk[8]*nr;

        __syncthreads();                 // previous row fully consumed
        *(float4*)&rowbuf[w][x0] = make_float4(o0, o1, o2, o3);

        pv = cv; pl = cl; pr = cr;
        cv = nv; cl = nl; cr = nr;
        loadrow(y + 2, nv, nl, nr);      // prefetch overlaps consume phase

        __syncthreads();                 // rowbuf ready
        float4 xin = *(const float4*)&xc[y * W_ + x0];
        float4 s = make_float4(xin.x + o0, xin.y + o1, xin.z + o2, xin.w + o3);
        #pragma unroll
        for (int d = 0; d < 8; d++) {
            float4 vd = *(const float4*)&rowbuf[d][x0];
            s.x += ar[d] * vd.x;
            s.y += ar[d] * vd.y;
            s.z += ar[d] * vd.z;
            s.w += ar[d] * vd.w;
        }
        *(float4*)&oc[y * W_ + x0] = s;
    }
}

// ---------------- launch -----------------------------------------------------------
extern "C" void kernel_launch(void* const* d_in, const int* in_sizes, int n_in,
                              void* d_out, int out_size)
{
    const float* hsi    = (const float*)d_in[0];
    const float* lidar  = (const float*)d_in[1];
    const float* hqkvw  = (const float*)d_in[2];
    const float* hqkvb  = (const float*)d_in[3];
    const float* lqkvw  = (const float*)d_in[4];
    const float* lqkvb  = (const float*)d_in[5];
    const float* hdww   = (const float*)d_in[6];
    const float* hdwb   = (const float*)d_in[7];
    const float* ldww   = (const float*)d_in[8];
    const float* ldwb   = (const float*)d_in[9];
    const float* temp1  = (const float*)d_in[10];
    const float* temp2  = (const float*)d_in[11];
    const float* projw  = (const float*)d_in[12];
    const float* projb  = (const float*)d_in[13];
    const float* gamma  = (const float*)d_in[14];
    const float* beta   = (const float*)d_in[15];
    const float* mean   = (const float*)d_in[16];
    const float* var    = (const float*)d_in[17];

    static cudaStream_t s2 = nullptr;
    static cudaEvent_t ev1 = nullptr, ev2 = nullptr;
    if (s2 == nullptr) {
        cudaStreamCreateWithFlags(&s2, cudaStreamNonBlocking);
        cudaEventCreateWithFlags(&ev1, cudaEventDisableTiming);
        cudaEventCreateWithFlags(&ev2, cudaEventDisableTiming);
        cudaFuncSetAttribute(k_gemm_mma, cudaFuncAttributeMaxDynamicSharedMemorySize,
                             GEMM_SMEM);
    }

    // q,k channels (m-tiles 0..7)
    k_gemm_mma<<<dim3(8, HW_ / 128, 4), 256, GEMM_SMEM>>>(
        hsi, lidar, hqkvw, hqkvb, lqkvw, lqkvb, 0);
    cudaEventRecord(ev1, 0);

    // side stream: attention path (depends only on q,k conv planes)
    cudaStreamWaitEvent(s2, ev1, 0);
    k_dwattn<<<dim3(HEADS_, B_, 2), 512, 0, s2>>>(hdww, hdwb, ldww, ldwb, temp1, temp2);
    k_fuse  <<<dim3(8, B_), 512, 0, s2>>>(projw, projb, gamma, beta, mean, var);
    cudaEventRecord(ev2, s2);

    // main stream: v channels (m-tiles 8..11) overlap with attention path
    k_gemm_mma<<<dim3(4, HW_ / 128, 4), 256, GEMM_SMEM>>>(
        hsi, lidar, hqkvw, hqkvb, lqkvw, lqkvb, 8);

    cudaStreamWaitEvent(0, ev2, 0);
    k_vout<<<dim3(HEADS_, 4), 256>>>(hsi, lidar, hdww, hdwb, ldww, ldwb, (float*)d_out);
}

// round 9
// speedup vs baseline: 1.0088x; 1.0088x over previous
#include <cuda_runtime.h>
#include <cuda_bf16.h>
#include <math.h>
#include <cstdint>

#define B_    2
#define C_    512
#define C3_   1536
#define H_    128
#define W_    128
#define HW_   16384
#define HEADS_ 64
#define CH_   8
#define PLANE_ (C3_ * HW_)
#define TENSOR_ ((size_t)B_ * C_ * HW_)

// ---------------- scratch ----------------
__device__ float g_conv[4][PLANE_];
__device__ float g_attn[2][B_][HEADS_][64];
__device__ float g_a[2][B_][HEADS_][64];

// ---------------- helpers ----------------
static __device__ __forceinline__ uint32_t s2u(const void* p) {
    uint32_t a;
    asm("{ .reg .u64 t; cvta.to.shared.u64 t, %1; cvt.u32.u64 %0, t; }"
        : "=r"(a) : "l"(p));
    return a;
}
static __device__ __forceinline__ void cpasync16(uint32_t dst, const void* src) {
    asm volatile("cp.async.cg.shared.global [%0], [%1], 16;" :: "r"(dst), "l"(src));
}
static __device__ __forceinline__ void cp_commit() {
    asm volatile("cp.async.commit_group;" ::: "memory");
}
template <int N>
static __device__ __forceinline__ void cp_wait() {
    asm volatile("cp.async.wait_group %0;" :: "n"(N) : "memory");
}
static __device__ __forceinline__ void mma_tf32(float& d0, float& d1, float& d2, float& d3,
                                                uint32_t a0, uint32_t a1, uint32_t a2, uint32_t a3,
                                                uint32_t b0, uint32_t b1) {
    asm volatile("mma.sync.aligned.m16n8k8.row.col.f32.tf32.tf32.f32 "
                 "{%0,%1,%2,%3}, {%4,%5,%6,%7}, {%8,%9}, {%0,%1,%2,%3};"
                 : "+f"(d0), "+f"(d1), "+f"(d2), "+f"(d3)
                 : "r"(a0), "r"(a1), "r"(a2), "r"(a3), "r"(b0), "r"(b1));
}

// ---------------- K1: tf32 mma.sync GEMM, 3-stage cp.async pipeline ----
#define BK_    16
#define APAD_  20
#define XPAD_  136
#define KITERS (C_ / BK_)   // 32
#define ST_    3
#define A_FLOATS (128 * APAD_)
#define X_FLOATS (BK_ * XPAD_)
#define GEMM_SMEM ((ST_ * (A_FLOATS + X_FLOATS)) * 4)   // 56832 B

__global__ __launch_bounds__(256, 2) void k_gemm_mma(
    const float* __restrict__ hsi, const float* __restrict__ lidar,
    const float* __restrict__ hw_w, const float* __restrict__ hw_b,
    const float* __restrict__ lw_w, const float* __restrict__ lw_b)
{
    extern __shared__ float smem_g[];
    float* Asm = smem_g;
    float* Xsm = smem_g + ST_ * A_FLOATS;

    const int tid  = threadIdx.x;
    const int lane = tid & 31;
    const int wid  = tid >> 5;
    const int g    = lane >> 2;
    const int c    = lane & 3;

    const int mb  = blockIdx.z;
    const int mod = mb >> 1, bb = mb & 1;
    const float* Wm   = mod ? lw_w : hw_w;
    const float* bias = mod ? lw_b : hw_b;
    const float* X = (mod ? lidar : hsi) + (size_t)bb * C_ * HW_;
    float* Y = g_conv[mb];
    const int m0 = blockIdx.x * 128;
    const int n0 = blockIdx.y * 128;

    const int warp_m = (wid & 1) * 64;
    const int warp_n = (wid >> 1) * 32;

    const int a_row0 = tid >> 2;
    const int a_gr   = tid & 3;

    const uint32_t asb = s2u(Asm);
    const uint32_t xsb = s2u(Xsm);

    float acc[4][4][4] = {};

    auto load_stage = [&](int s, int k0) {
        #pragma unroll
        for (int i = 0; i < 2; i++) {
            int row = a_row0 + 64 * i;
            cpasync16(asb + (s * A_FLOATS + row * APAD_ + a_gr * 4) * 4,
                      &Wm[(size_t)(m0 + row) * C_ + k0 + a_gr * 4]);
        }
        #pragma unroll
        for (int i = 0; i < 2; i++) {
            int idx = tid + 256 * i;
            int kk  = idx >> 5;
            int gr  = idx & 31;
            cpasync16(xsb + (s * X_FLOATS + kk * XPAD_ + gr * 4) * 4,
                      &X[(size_t)(k0 + kk) * HW_ + n0 + gr * 4]);
        }
    };

    load_stage(0, 0);
    cp_commit();
    load_stage(1, BK_);
    cp_commit();

    for (int it = 0; it < KITERS; it++) {
        const int s = it % ST_;
        cp_wait<1>();
        __syncthreads();

        const float* Ap = &Asm[s * A_FLOATS];
        const float* Xp = &Xsm[s * X_FLOATS];
        #pragma unroll
        for (int ks = 0; ks < BK_; ks += 8) {
            uint32_t af[4][4], bf[4][2];
            #pragma unroll
            for (int i = 0; i < 4; i++) {
                int row = warp_m + 16 * i + g;
                af[i][0] = __float_as_uint(Ap[row * APAD_ + ks + c]);
                af[i][1] = __float_as_uint(Ap[(row + 8) * APAD_ + ks + c]);
                af[i][2] = __float_as_uint(Ap[row * APAD_ + ks + c + 4]);
                af[i][3] = __float_as_uint(Ap[(row + 8) * APAD_ + ks + c + 4]);
            }
            #pragma unroll
            for (int j = 0; j < 4; j++) {
                int col = warp_n + 8 * j + g;
                bf[j][0] = __float_as_uint(Xp[(ks + c) * XPAD_ + col]);
                bf[j][1] = __float_as_uint(Xp[(ks + c + 4) * XPAD_ + col]);
            }
            #pragma unroll
            for (int i = 0; i < 4; i++)
                #pragma unroll
                for (int j = 0; j < 4; j++)
                    mma_tf32(acc[i][j][0], acc[i][j][1], acc[i][j][2], acc[i][j][3],
                             af[i][0], af[i][1], af[i][2], af[i][3],
                             bf[j][0], bf[j][1]);
        }
        const int nxt = it + 2;
        if (nxt < KITERS) load_stage(nxt % ST_, nxt * BK_);
        cp_commit();
    }

    #pragma unroll
    for (int i = 0; i < 4; i++) {
        const int r0 = m0 + warp_m + 16 * i + g;
        const float bi0 = bias[r0];
        const float bi1 = bias[r0 + 8];
        #pragma unroll
        for (int j = 0; j < 4; j++) {
            const int col = n0 + warp_n + 8 * j + 2 * c;
            *(float2*)&Y[(size_t)r0 * HW_ + col] =
                make_float2(acc[i][j][0] + bi0, acc[i][j][1] + bi0);
            *(float2*)&Y[(size_t)(r0 + 8) * HW_ + col] =
                make_float2(acc[i][j][2] + bi1, acc[i][j][3] + bi1);
        }
    }
}

// ---------------- K3: fused dwconv(q,k) + ssq + channel-attention dot ----
__global__ __launch_bounds__(512) void k_dwattn(
    const float* __restrict__ hdww, const float* __restrict__ hdwb,
    const float* __restrict__ ldww, const float* __restrict__ ldwb,
    const float* __restrict__ temp1, const float* __restrict__ temp2)
{
    __shared__ float rowbuf[16][132];
    __shared__ float sq[16];
    __shared__ float red[4][16][4];

    const int h = blockIdx.x, bb = blockIdx.y, a = blockIdx.z;
    const int tid = threadIdx.x;
    const int w = tid >> 5, lane = tid & 31;

    const int isk = w >> 3;
    const int ch  = w & 7;
    const int mod = isk ? (1 - a) : a;
    const int plane = (isk ? C_ : 0) + h * CH_ + ch;
    const float* src = g_conv[mod * 2 + bb] + (size_t)plane * HW_;
    const float* wp  = (mod ? ldww : hdww) + plane * 9;
    float wk[9];
    #pragma unroll
    for (int t = 0; t < 9; t++) wk[t] = __ldg(&wp[t]);
    const float bias = (mod ? ldwb : hdwb)[plane];

    const int x0 = lane * 4;

    float4 pv, cv, nv;
    float pl, pr, cl, cr, nl, nr;
    auto loadrow = [&](int y, float4& v, float& l, float& r) {
        if (y < 0 || y >= H_) { v = make_float4(0.f,0.f,0.f,0.f); l = 0.f; r = 0.f; return; }
        v = *(const float4*)&src[y * W_ + x0];
        l = __shfl_up_sync(0xffffffffu, v.w, 1);
        if (lane == 0) l = 0.f;
        r = __shfl_down_sync(0xffffffffu, v.x, 1);
        if (lane == 31) r = 0.f;
    };
    pv = make_float4(0.f,0.f,0.f,0.f); pl = pr = 0.f;
    loadrow(0, cv, cl, cr);
    loadrow(1, nv, nl, nr);

    const int xq  = tid & 127;
    const int blk = tid >> 7;
    const int c0  = (blk & 1) * 4;
    const int d0  = (blk >> 1) * 4;

    float ssq = 0.f;
    float acc[4][4] = {};

    for (int y = 0; y < H_; y++) {
        float o0 = bias
            + wk[0]*pl   + wk[1]*pv.x + wk[2]*pv.y
            + wk[3]*cl   + wk[4]*cv.x + wk[5]*cv.y
            + wk[6]*nl   + wk[7]*nv.x + wk[8]*nv.y;
        float o1 = bias
            + wk[0]*pv.x + wk[1]*pv.y + wk[2]*pv.z
            + wk[3]*cv.x + wk[4]*cv.y + wk[5]*cv.z
            + wk[6]*nv.x + wk[7]*nv.y + wk[8]*nv.z;
        float o2 = bias
            + wk[0]*pv.y + wk[1]*pv.z + wk[2]*pv.w
            + wk[3]*cv.y + wk[4]*cv.z + wk[5]*cv.w
            + wk[6]*nv.y + wk[7]*nv.z + wk[8]*nv.w;
        float o3 = bias
            + wk[0]*pv.z + wk[1]*pv.w + wk[2]*pr
            + wk[3]*cv.z + wk[4]*cv.w + wk[5]*cr
            + wk[6]*nv.z + wk[7]*nv.w + wk[8]*nr;

        __syncthreads();
        *(float4*)&rowbuf[w][x0] = make_float4(o0, o1, o2, o3);
        ssq += o0*o0 + o1*o1 + o2*o2 + o3*o3;

        pv = cv; pl = cl; pr = cr;
        cv = nv; cl = nl; cr = nr;
        loadrow(y + 2, nv, nl, nr);

        __syncthreads();
        float qv[4], kv[4];
        #pragma unroll
        for (int i = 0; i < 4; i++) qv[i] = rowbuf[c0 + i][xq];
        #pragma unroll
        for (int j = 0; j < 4; j++) kv[j] = rowbuf[8 + d0 + j][xq];
        #pragma unroll
        for (int i = 0; i < 4; i++)
            #pragma unroll
            for (int j = 0; j < 4; j++)
                acc[i][j] += qv[i] * kv[j];
    }

    #pragma unroll
    for (int off = 16; off; off >>= 1)
        ssq += __shfl_down_sync(0xffffffffu, ssq, off);
    if (lane == 0) sq[w] = ssq;

    const int wsub = (tid >> 5) & 3;
    #pragma unroll
    for (int i = 0; i < 4; i++)
        #pragma unroll
        for (int j = 0; j < 4; j++) {
            float v = acc[i][j];
            #pragma unroll
            for (int off = 16; off; off >>= 1)
                v += __shfl_down_sync(0xffffffffu, v, off);
            if (lane == 0) red[blk][i * 4 + j][wsub] = v;
        }
    __syncthreads();

    if (tid < 64) {
        int cc = tid >> 3, dd = tid & 7;
        int bq = (cc >> 2) + ((dd >> 2) << 1);
        int ii = cc & 3, jj = dd & 3;
        float dot = red[bq][ii * 4 + jj][0] + red[bq][ii * 4 + jj][1]
                  + red[bq][ii * 4 + jj][2] + red[bq][ii * 4 + jj][3];
        float qn = fmaxf(sqrtf(sq[cc]), 1e-12f);
        float kn = fmaxf(sqrtf(sq[8 + dd]), 1e-12f);
        float tmp = (a == 0 ? temp1 : temp2)[h];
        g_attn[a][bb][h][tid] = dot / (qn * kn) * tmp;
    }
}

// ---------------- K4: score fusion + BN + ReLU + softmax (smem-staged) ---------
__global__ __launch_bounds__(512) void k_fuse(
    const float* __restrict__ projw, const float* __restrict__ projb,
    const float* __restrict__ gamma, const float* __restrict__ beta,
    const float* __restrict__ mean,  const float* __restrict__ var)
{
    __shared__ float attn_s[2][64][64];   // 32 KB
    const int ogrp = blockIdx.x, bb = blockIdx.y;
    const int tid = threadIdx.x;

    for (int i = tid; i < 2 * 64 * 64; i += 512) {
        int aa = i >> 12, rest = i & 4095;
        attn_s[aa][rest >> 6][rest & 63] = g_attn[aa][bb][rest >> 6][rest & 63];
    }
    __syncthreads();

    const int o  = ogrp * 8 + (tid >> 6);
    const int cd = tid & 63;
    const float* w = projw + o * 128;
    float s = __ldg(&projb[o]);
    #pragma unroll 8
    for (int i = 0; i < 64; i++) s += __ldg(&w[i])      * attn_s[0][i][cd];
    #pragma unroll 8
    for (int i = 0; i < 64; i++) s += __ldg(&w[64 + i]) * attn_s[1][i][cd];
    s = (s - __ldg(&mean[o])) * rsqrtf(__ldg(&var[o]) + 1e-5f) * __ldg(&gamma[o]) + __ldg(&beta[o]);
    s = fmaxf(s, 0.f);
    #pragma unroll
    for (int a = 0; a < 2; a++) {
        float v = s + attn_s[a][o][cd];
        float m = v;
        #pragma unroll
        for (int off = 4; off; off >>= 1)
            m = fmaxf(m, __shfl_xor_sync(0xffffffffu, m, off, 8));
        float e = expf(v - m);
        float su = e;
        #pragma unroll
        for (int off = 4; off; off >>= 1)
            su += __shfl_xor_sync(0xffffffffu, su, off, 8);
        g_a[a][bb][o][cd] = e / su;
    }
}

// ---------------- K5: fused dwconv(v) + (a @ v + v + x) -----------------------
__global__ __launch_bounds__(256) void k_vout(
    const float* __restrict__ hsi, const float* __restrict__ lidar,
    const float* __restrict__ hdww, const float* __restrict__ hdwb,
    const float* __restrict__ ldww, const float* __restrict__ ldwb,
    float* __restrict__ out)
{
    __shared__ float rowbuf[8][132];

    const int h = blockIdx.x, mb = blockIdx.y;
    const int mod = mb >> 1, bb = mb & 1;
    const int tid = threadIdx.x;
    const int w = tid >> 5, lane = tid & 31;

    const int plane = 2 * C_ + h * CH_ + w;
    const float* src = g_conv[mb] + (size_t)plane * HW_;
    const float* wp  = (mod ? ldww : hdww) + plane * 9;
    float wk[9];
    #pragma unroll
    for (int t = 0; t < 9; t++) wk[t] = __ldg(&wp[t]);
    const float bias = (mod ? ldwb : hdwb)[plane];

    float ar[8];
    #pragma unroll
    for (int d = 0; d < 8; d++) ar[d] = __ldg(&g_a[mod][bb][h][w * 8 + d]);

    const float* xc = (mod ? lidar : hsi) + (size_t)(bb * C_ + h * CH_ + w) * HW_;
    float* oc = out + (size_t)mod * TENSOR_ + (size_t)(bb * C_ + h * CH_ + w) * HW_;

    const int x0 = lane * 4;

    float4 pv, cv, nv;
    float pl, pr, cl, cr, nl, nr;
    auto loadrow = [&](int y, float4& v, float& l, float& r) {
        if (y < 0 || y >= H_) { v = make_float4(0.f,0.f,0.f,0.f); l = 0.f; r = 0.f; return; }
        v = *(const float4*)&src[y * W_ + x0];
        l = __shfl_up_sync(0xffffffffu, v.w, 1);
        if (lane == 0) l = 0.f;
        r = __shfl_down_sync(0xffffffffu, v.x, 1);
        if (lane == 31) r = 0.f;
    };
    pv = make_float4(0.f,0.f,0.f,0.f); pl = pr = 0.f;
    loadrow(0, cv, cl, cr);
    loadrow(1, nv, nl, nr);

    for (int y = 0; y < H_; y++) {
        float o0 = bias
            + wk[0]*pl   + wk[1]*pv.x + wk[2]*pv.y
            + wk[3]*cl   + wk[4]*cv.x + wk[5]*cv.y
            + wk[6]*nl   + wk[7]*nv.x + wk[8]*nv.y;
        float o1 = bias
            + wk[0]*pv.x + wk[1]*pv.y + wk[2]*pv.z
            + wk[3]*cv.x + wk[4]*cv.y + wk[5]*cv.z
            + wk[6]*nv.x + wk[7]*nv.y + wk[8]*nv.z;
        float o2 = bias
            + wk[0]*pv.y + wk[1]*pv.z + wk[2]*pv.w
            + wk[3]*cv.y + wk[4]*cv.z + wk[5]*cv.w
            + wk[6]*nv.y + wk[7]*nv.z + wk[8]*nv.w;
        float o3 = bias
            + wk[0]*pv.z + wk[1]*pv.w + wk[2]*pr
            + wk[3]*cv.z + wk[4]*cv.w + wk[5]*cr
            + wk[6]*nv.z + wk[7]*nv.w + wk[8]*nr;

        __syncthreads();
        *(float4*)&rowbuf[w][x0] = make_float4(o0, o1, o2, o3);

        pv = cv; pl = cl; pr = cr;
        cv = nv; cl = nl; cr = nr;
        loadrow(y + 2, nv, nl, nr);

        __syncthreads();
        float4 xin = *(const float4*)&xc[y * W_ + x0];
        float4 s = make_float4(xin.x + o0, xin.y + o1, xin.z + o2, xin.w + o3);
        #pragma unroll
        for (int d = 0; d < 8; d++) {
            float4 vd = *(const float4*)&rowbuf[d][x0];
            s.x += ar[d] * vd.x;
            s.y += ar[d] * vd.y;
            s.z += ar[d] * vd.z;
            s.w += ar[d] * vd.w;
        }
        *(float4*)&oc[y * W_ + x0] = s;
    }
}

// ---------------- launch -----------------------------------------------------------
extern "C" void kernel_launch(void* const* d_in, const int* in_sizes, int n_in,
                              void* d_out, int out_size)
{
    const float* hsi    = (const float*)d_in[0];
    const float* lidar  = (const float*)d_in[1];
    const float* hqkvw  = (const float*)d_in[2];
    const float* hqkvb  = (const float*)d_in[3];
    const float* lqkvw  = (const float*)d_in[4];
    const float* lqkvb  = (const float*)d_in[5];
    const float* hdww   = (const float*)d_in[6];
    const float* hdwb   = (const float*)d_in[7];
    const float* ldww   = (const float*)d_in[8];
    const float* ldwb   = (const float*)d_in[9];
    const float* temp1  = (const float*)d_in[10];
    const float* temp2  = (const float*)d_in[11];
    const float* projw  = (const float*)d_in[12];
    const float* projb  = (const float*)d_in[13];
    const float* gamma  = (const float*)d_in[14];
    const float* beta   = (const float*)d_in[15];
    const float* mean   = (const float*)d_in[16];
    const float* var    = (const float*)d_in[17];

    cudaFuncSetAttribute(k_gemm_mma, cudaFuncAttributeMaxDynamicSharedMemorySize,
                         GEMM_SMEM);
    k_gemm_mma<<<dim3(C3_ / 128, HW_ / 128, 4), 256, GEMM_SMEM>>>(
        hsi, lidar, hqkvw, hqkvb, lqkvw, lqkvb);
    k_dwattn<<<dim3(HEADS_, B_, 2), 512>>>(hdww, hdwb, ldww, ldwb, temp1, temp2);
    k_fuse  <<<dim3(8, B_), 512>>>(projw, projb, gamma, beta, mean, var);
    k_vout  <<<dim3(HEADS_, 4), 256>>>(hsi, lidar, hdww, hdwb, ldww, ldwb, (float*)d_out);
}

// round 10
// speedup vs baseline: 1.0924x; 1.0828x over previous
#include <cuda_runtime.h>
#include <cuda_bf16.h>
#include <math.h>
#include <cstdint>

#define B_    2
#define C_    512
#define C3_   1536
#define H_    128
#define W_    128
#define HW_   16384
#define HEADS_ 64
#define CH_   8
#define PLANE_ (C3_ * HW_)
#define TENSOR_ ((size_t)B_ * C_ * HW_)
#define YT_   4
#define YROWS_ (H_ / YT_)   // 32

// ---------------- scratch ----------------
__device__ float g_conv[4][PLANE_];
__device__ float g_attn[2][B_][HEADS_][64];
__device__ float g_a[2][B_][HEADS_][64];
__device__ float g_pdot[2][B_][HEADS_][YT_][64];
__device__ float g_psq[2][B_][HEADS_][YT_][16];

// ---------------- helpers ----------------
static __device__ __forceinline__ uint32_t s2u(const void* p) {
    uint32_t a;
    asm("{ .reg .u64 t; cvta.to.shared.u64 t, %1; cvt.u32.u64 %0, t; }"
        : "=r"(a) : "l"(p));
    return a;
}
static __device__ __forceinline__ void cpasync16(uint32_t dst, const void* src) {
    asm volatile("cp.async.cg.shared.global [%0], [%1], 16;" :: "r"(dst), "l"(src));
}
static __device__ __forceinline__ void cp_commit() {
    asm volatile("cp.async.commit_group;" ::: "memory");
}
template <int N>
static __device__ __forceinline__ void cp_wait() {
    asm volatile("cp.async.wait_group %0;" :: "n"(N) : "memory");
}
static __device__ __forceinline__ void mma_tf32(float& d0, float& d1, float& d2, float& d3,
                                                uint32_t a0, uint32_t a1, uint32_t a2, uint32_t a3,
                                                uint32_t b0, uint32_t b1) {
    asm volatile("mma.sync.aligned.m16n8k8.row.col.f32.tf32.tf32.f32 "
                 "{%0,%1,%2,%3}, {%4,%5,%6,%7}, {%8,%9}, {%0,%1,%2,%3};"
                 : "+f"(d0), "+f"(d1), "+f"(d2), "+f"(d3)
                 : "r"(a0), "r"(a1), "r"(a2), "r"(a3), "r"(b0), "r"(b1));
}

// ---------------- K1: tf32 mma.sync GEMM, 3-stage cp.async pipeline ----
#define BK_    16
#define APAD_  20
#define XPAD_  136
#define KITERS (C_ / BK_)   // 32
#define ST_    3
#define A_FLOATS (128 * APAD_)
#define X_FLOATS (BK_ * XPAD_)
#define GEMM_SMEM ((ST_ * (A_FLOATS + X_FLOATS)) * 4)   // 56832 B

__global__ __launch_bounds__(256, 2) void k_gemm_mma(
    const float* __restrict__ hsi, const float* __restrict__ lidar,
    const float* __restrict__ hw_w, const float* __restrict__ hw_b,
    const float* __restrict__ lw_w, const float* __restrict__ lw_b)
{
    extern __shared__ float smem_g[];
    float* Asm = smem_g;
    float* Xsm = smem_g + ST_ * A_FLOATS;

    const int tid  = threadIdx.x;
    const int lane = tid & 31;
    const int wid  = tid >> 5;
    const int g    = lane >> 2;
    const int c    = lane & 3;

    const int mb  = blockIdx.z;
    const int mod = mb >> 1, bb = mb & 1;
    const float* Wm   = mod ? lw_w : hw_w;
    const float* bias = mod ? lw_b : hw_b;
    const float* X = (mod ? lidar : hsi) + (size_t)bb * C_ * HW_;
    float* Y = g_conv[mb];
    const int m0 = blockIdx.x * 128;
    const int n0 = blockIdx.y * 128;

    const int warp_m = (wid & 1) * 64;
    const int warp_n = (wid >> 1) * 32;

    const int a_row0 = tid >> 2;
    const int a_gr   = tid & 3;

    const uint32_t asb = s2u(Asm);
    const uint32_t xsb = s2u(Xsm);

    float acc[4][4][4] = {};

    auto load_stage = [&](int s, int k0) {
        #pragma unroll
        for (int i = 0; i < 2; i++) {
            int row = a_row0 + 64 * i;
            cpasync16(asb + (s * A_FLOATS + row * APAD_ + a_gr * 4) * 4,
                      &Wm[(size_t)(m0 + row) * C_ + k0 + a_gr * 4]);
        }
        #pragma unroll
        for (int i = 0; i < 2; i++) {
            int idx = tid + 256 * i;
            int kk  = idx >> 5;
            int gr  = idx & 31;
            cpasync16(xsb + (s * X_FLOATS + kk * XPAD_ + gr * 4) * 4,
                      &X[(size_t)(k0 + kk) * HW_ + n0 + gr * 4]);
        }
    };

    load_stage(0, 0);
    cp_commit();
    load_stage(1, BK_);
    cp_commit();

    for (int it = 0; it < KITERS; it++) {
        const int s = it % ST_;
        cp_wait<1>();
        __syncthreads();

        const float* Ap = &Asm[s * A_FLOATS];
        const float* Xp = &Xsm[s * X_FLOATS];
        #pragma unroll
        for (int ks = 0; ks < BK_; ks += 8) {
            uint32_t af[4][4], bf[4][2];
            #pragma unroll
            for (int i = 0; i < 4; i++) {
                int row = warp_m + 16 * i + g;
                af[i][0] = __float_as_uint(Ap[row * APAD_ + ks + c]);
                af[i][1] = __float_as_uint(Ap[(row + 8) * APAD_ + ks + c]);
                af[i][2] = __float_as_uint(Ap[row * APAD_ + ks + c + 4]);
                af[i][3] = __float_as_uint(Ap[(row + 8) * APAD_ + ks + c + 4]);
            }
            #pragma unroll
            for (int j = 0; j < 4; j++) {
                int col = warp_n + 8 * j + g;
                bf[j][0] = __float_as_uint(Xp[(ks + c) * XPAD_ + col]);
                bf[j][1] = __float_as_uint(Xp[(ks + c + 4) * XPAD_ + col]);
            }
            #pragma unroll
            for (int i = 0; i < 4; i++)
                #pragma unroll
                for (int j = 0; j < 4; j++)
                    mma_tf32(acc[i][j][0], acc[i][j][1], acc[i][j][2], acc[i][j][3],
                             af[i][0], af[i][1], af[i][2], af[i][3],
                             bf[j][0], bf[j][1]);
        }
        const int nxt = it + 2;
        if (nxt < KITERS) load_stage(nxt % ST_, nxt * BK_);
        cp_commit();
    }

    #pragma unroll
    for (int i = 0; i < 4; i++) {
        const int r0 = m0 + warp_m + 16 * i + g;
        const float bi0 = bias[r0];
        const float bi1 = bias[r0 + 8];
        #pragma unroll
        for (int j = 0; j < 4; j++) {
            const int col = n0 + warp_n + 8 * j + 2 * c;
            *(float2*)&Y[(size_t)r0 * HW_ + col] =
                make_float2(acc[i][j][0] + bi0, acc[i][j][1] + bi0);
            *(float2*)&Y[(size_t)(r0 + 8) * HW_ + col] =
                make_float2(acc[i][j][2] + bi1, acc[i][j][3] + bi1);
        }
    }
}

// ---------------- K3: fused dwconv(q,k) + partial ssq + partial channel dot ----
// grid: (h + 64*yt = 256, bb=2, a=2). Each block covers 32 rows of the plane.
__global__ __launch_bounds__(512) void k_dwattn(
    const float* __restrict__ hdww, const float* __restrict__ hdwb,
    const float* __restrict__ ldww, const float* __restrict__ ldwb)
{
    __shared__ float rowbuf[16][132];
    __shared__ float red[4][16][4];

    const int h = blockIdx.x & 63, yt = blockIdx.x >> 6;
    const int bb = blockIdx.y, a = blockIdx.z;
    const int y0 = yt * YROWS_;
    const int tid = threadIdx.x;
    const int w = tid >> 5, lane = tid & 31;

    const int isk = w >> 3;
    const int ch  = w & 7;
    const int mod = isk ? (1 - a) : a;
    const int plane = (isk ? C_ : 0) + h * CH_ + ch;
    const float* src = g_conv[mod * 2 + bb] + (size_t)plane * HW_;
    const float* wp  = (mod ? ldww : hdww) + plane * 9;
    float wk[9];
    #pragma unroll
    for (int t = 0; t < 9; t++) wk[t] = __ldg(&wp[t]);
    const float bias = (mod ? ldwb : hdwb)[plane];

    const int x0 = lane * 4;

    float4 pv, cv, nv;
    float pl, pr, cl, cr, nl, nr;
    auto loadrow = [&](int y, float4& v, float& l, float& r) {
        if (y < 0 || y >= H_) { v = make_float4(0.f,0.f,0.f,0.f); l = 0.f; r = 0.f; return; }
        v = *(const float4*)&src[y * W_ + x0];
        l = __shfl_up_sync(0xffffffffu, v.w, 1);
        if (lane == 0) l = 0.f;
        r = __shfl_down_sync(0xffffffffu, v.x, 1);
        if (lane == 31) r = 0.f;
    };
    loadrow(y0 - 1, pv, pl, pr);
    loadrow(y0,     cv, cl, cr);
    loadrow(y0 + 1, nv, nl, nr);

    const int xq  = tid & 127;
    const int blk = tid >> 7;
    const int c0  = (blk & 1) * 4;
    const int d0  = (blk >> 1) * 4;

    float ssq = 0.f;
    float acc[4][4] = {};

    for (int y = y0; y < y0 + YROWS_; y++) {
        float o0 = bias
            + wk[0]*pl   + wk[1]*pv.x + wk[2]*pv.y
            + wk[3]*cl   + wk[4]*cv.x + wk[5]*cv.y
            + wk[6]*nl   + wk[7]*nv.x + wk[8]*nv.y;
        float o1 = bias
            + wk[0]*pv.x + wk[1]*pv.y + wk[2]*pv.z
            + wk[3]*cv.x + wk[4]*cv.y + wk[5]*cv.z
            + wk[6]*nv.x + wk[7]*nv.y + wk[8]*nv.z;
        float o2 = bias
            + wk[0]*pv.y + wk[1]*pv.z + wk[2]*pv.w
            + wk[3]*cv.y + wk[4]*cv.z + wk[5]*cv.w
            + wk[6]*nv.y + wk[7]*nv.z + wk[8]*nv.w;
        float o3 = bias
            + wk[0]*pv.z + wk[1]*pv.w + wk[2]*pr
            + wk[3]*cv.z + wk[4]*cv.w + wk[5]*cr
            + wk[6]*nv.z + wk[7]*nv.w + wk[8]*nr;

        __syncthreads();
        *(float4*)&rowbuf[w][x0] = make_float4(o0, o1, o2, o3);
        ssq += o0*o0 + o1*o1 + o2*o2 + o3*o3;

        pv = cv; pl = cl; pr = cr;
        cv = nv; cl = nl; cr = nr;
        loadrow(y + 2, nv, nl, nr);

        __syncthreads();
        float qv[4], kv[4];
        #pragma unroll
        for (int i = 0; i < 4; i++) qv[i] = rowbuf[c0 + i][xq];
        #pragma unroll
        for (int j = 0; j < 4; j++) kv[j] = rowbuf[8 + d0 + j][xq];
        #pragma unroll
        for (int i = 0; i < 4; i++)
            #pragma unroll
            for (int j = 0; j < 4; j++)
                acc[i][j] += qv[i] * kv[j];
    }

    #pragma unroll
    for (int off = 16; off; off >>= 1)
        ssq += __shfl_down_sync(0xffffffffu, ssq, off);
    if (lane == 0) g_psq[a][bb][h][yt][w] = ssq;

    const int wsub = (tid >> 5) & 3;
    #pragma unroll
    for (int i = 0; i < 4; i++)
        #pragma unroll
        for (int j = 0; j < 4; j++) {
            float v = acc[i][j];
            #pragma unroll
            for (int off = 16; off; off >>= 1)
                v += __shfl_down_sync(0xffffffffu, v, off);
            if (lane == 0) red[blk][i * 4 + j][wsub] = v;
        }
    __syncthreads();

    if (tid < 64) {
        int cc = tid >> 3, dd = tid & 7;
        int bq = (cc >> 2) + ((dd >> 2) << 1);
        int ii = cc & 3, jj = dd & 3;
        g_pdot[a][bb][h][yt][tid] =
            red[bq][ii * 4 + jj][0] + red[bq][ii * 4 + jj][1]
          + red[bq][ii * 4 + jj][2] + red[bq][ii * 4 + jj][3];
    }
}

// ---------------- K3b: combine partials -> attn ----
__global__ __launch_bounds__(64) void k_comb(
    const float* __restrict__ temp1, const float* __restrict__ temp2)
{
    const int h = blockIdx.x, bb = blockIdx.y, a = blockIdx.z;
    const int tid = threadIdx.x;
    const int cc = tid >> 3, dd = tid & 7;
    float dot = 0.f;
    #pragma unroll
    for (int yt = 0; yt < YT_; yt++) dot += g_pdot[a][bb][h][yt][tid];
    float qs = 0.f, ks = 0.f;
    #pragma unroll
    for (int yt = 0; yt < YT_; yt++) {
        qs += g_psq[a][bb][h][yt][cc];
        ks += g_psq[a][bb][h][yt][8 + dd];
    }
    float qn = fmaxf(sqrtf(qs), 1e-12f);
    float kn = fmaxf(sqrtf(ks), 1e-12f);
    float tmp = (a == 0 ? temp1 : temp2)[h];
    g_attn[a][bb][h][tid] = dot / (qn * kn) * tmp;
}

// ---------------- K4: score fusion + BN + ReLU + softmax (smem-staged) ---------
__global__ __launch_bounds__(512) void k_fuse(
    const float* __restrict__ projw, const float* __restrict__ projb,
    const float* __restrict__ gamma, const float* __restrict__ beta,
    const float* __restrict__ mean,  const float* __restrict__ var)
{
    __shared__ float attn_s[2][64][64];   // 32 KB
    const int ogrp = blockIdx.x, bb = blockIdx.y;
    const int tid = threadIdx.x;

    for (int i = tid; i < 2 * 64 * 64; i += 512) {
        int aa = i >> 12, rest = i & 4095;
        attn_s[aa][rest >> 6][rest & 63] = g_attn[aa][bb][rest >> 6][rest & 63];
    }
    __syncthreads();

    const int o  = ogrp * 8 + (tid >> 6);
    const int cd = tid & 63;
    const float* w = projw + o * 128;
    float s = __ldg(&projb[o]);
    #pragma unroll 8
    for (int i = 0; i < 64; i++) s += __ldg(&w[i])      * attn_s[0][i][cd];
    #pragma unroll 8
    for (int i = 0; i < 64; i++) s += __ldg(&w[64 + i]) * attn_s[1][i][cd];
    s = (s - __ldg(&mean[o])) * rsqrtf(__ldg(&var[o]) + 1e-5f) * __ldg(&gamma[o]) + __ldg(&beta[o]);
    s = fmaxf(s, 0.f);
    #pragma unroll
    for (int a = 0; a < 2; a++) {
        float v = s + attn_s[a][o][cd];
        float m = v;
        #pragma unroll
        for (int off = 4; off; off >>= 1)
            m = fmaxf(m, __shfl_xor_sync(0xffffffffu, m, off, 8));
        float e = expf(v - m);
        float su = e;
        #pragma unroll
        for (int off = 4; off; off >>= 1)
            su += __shfl_xor_sync(0xffffffffu, su, off, 8);
        g_a[a][bb][o][cd] = e / su;
    }
}

// ---------------- K5: fused dwconv(v) + (a @ v + v + x), y-tiled -----------------
// grid: (h=64, mb=4, yt=4). 256 threads = 8 warps; warp w owns v-channel w.
__global__ __launch_bounds__(256) void k_vout(
    const float* __restrict__ hsi, const float* __restrict__ lidar,
    const float* __restrict__ hdww, const float* __restrict__ hdwb,
    const float* __restrict__ ldww, const float* __restrict__ ldwb,
    float* __restrict__ out)
{
    __shared__ float rowbuf[8][132];

    const int h = blockIdx.x, mb = blockIdx.y, yt = blockIdx.z;
    const int y0 = yt * YROWS_;
    const int mod = mb >> 1, bb = mb & 1;
    const int tid = threadIdx.x;
    const int w = tid >> 5, lane = tid & 31;

    const int plane = 2 * C_ + h * CH_ + w;
    const float* src = g_conv[mb] + (size_t)plane * HW_;
    const float* wp  = (mod ? ldww : hdww) + plane * 9;
    float wk[9];
    #pragma unroll
    for (int t = 0; t < 9; t++) wk[t] = __ldg(&wp[t]);
    const float bias = (mod ? ldwb : hdwb)[plane];

    float ar[8];
    #pragma unroll
    for (int d = 0; d < 8; d++) ar[d] = __ldg(&g_a[mod][bb][h][w * 8 + d]);

    const float* xc = (mod ? lidar : hsi) + (size_t)(bb * C_ + h * CH_ + w) * HW_;
    float* oc = out + (size_t)mod * TENSOR_ + (size_t)(bb * C_ + h * CH_ + w) * HW_;

    const int x0 = lane * 4;

    float4 pv, cv, nv;
    float pl, pr, cl, cr, nl, nr;
    auto loadrow = [&](int y, float4& v, float& l, float& r) {
        if (y < 0 || y >= H_) { v = make_float4(0.f,0.f,0.f,0.f); l = 0.f; r = 0.f; return; }
        v = *(const float4*)&src[y * W_ + x0];
        l = __shfl_up_sync(0xffffffffu, v.w, 1);
        if (lane == 0) l = 0.f;
        r = __shfl_down_sync(0xffffffffu, v.x, 1);
        if (lane == 31) r = 0.f;
    };
    loadrow(y0 - 1, pv, pl, pr);
    loadrow(y0,     cv, cl, cr);
    loadrow(y0 + 1, nv, nl, nr);

    for (int y = y0; y < y0 + YROWS_; y++) {
        float o0 = bias
            + wk[0]*pl   + wk[1]*pv.x + wk[2]*pv.y
            + wk[3]*cl   + wk[4]*cv.x + wk[5]*cv.y
            + wk[6]*nl   + wk[7]*nv.x + wk[8]*nv.y;
        float o1 = bias
            + wk[0]*pv.x + wk[1]*pv.y + wk[2]*pv.z
            + wk[3]*cv.x + wk[4]*cv.y + wk[5]*cv.z
            + wk[6]*nv.x + wk[7]*nv.y + wk[8]*nv.z;
        float o2 = bias
            + wk[0]*pv.y + wk[1]*pv.z + wk[2]*pv.w
            + wk[3]*cv.y + wk[4]*cv.z + wk[5]*cv.w
            + wk[6]*nv.y + wk[7]*nv.z + wk[8]*nv.w;
        float o3 = bias
            + wk[0]*pv.z + wk[1]*pv.w + wk[2]*pr
            + wk[3]*cv.z + wk[4]*cv.w + wk[5]*cr
            + wk[6]*nv.z + wk[7]*nv.w + wk[8]*nr;

        __syncthreads();
        *(float4*)&rowbuf[w][x0] = make_float4(o0, o1, o2, o3);

        pv = cv; pl = cl; pr = cr;
        cv = nv; cl = nl; cr = nr;
        loadrow(y + 2, nv, nl, nr);

        __syncthreads();
        float4 xin = *(const float4*)&xc[y * W_ + x0];
        float4 s = make_float4(xin.x + o0, xin.y + o1, xin.z + o2, xin.w + o3);
        #pragma unroll
        for (int d = 0; d < 8; d++) {
            float4 vd = *(const float4*)&rowbuf[d][x0];
            s.x += ar[d] * vd.x;
            s.y += ar[d] * vd.y;
            s.z += ar[d] * vd.z;
            s.w += ar[d] * vd.w;
        }
        *(float4*)&oc[y * W_ + x0] = s;
    }
}

// ---------------- launch -----------------------------------------------------------
extern "C" void kernel_launch(void* const* d_in, const int* in_sizes, int n_in,
                              void* d_out, int out_size)
{
    const float* hsi    = (const float*)d_in[0];
    const float* lidar  = (const float*)d_in[1];
    const float* hqkvw  = (const float*)d_in[2];
    const float* hqkvb  = (const float*)d_in[3];
    const float* lqkvw  = (const float*)d_in[4];
    const float* lqkvb  = (const float*)d_in[5];
    const float* hdww   = (const float*)d_in[6];
    const float* hdwb   = (const float*)d_in[7];
    const float* ldww   = (const float*)d_in[8];
    const float* ldwb   = (const float*)d_in[9];
    const float* temp1  = (const float*)d_in[10];
    const float* temp2  = (const float*)d_in[11];
    const float* projw  = (const float*)d_in[12];
    const float* projb  = (const float*)d_in[13];
    const float* gamma  = (const float*)d_in[14];
    const float* beta   = (const float*)d_in[15];
    const float* mean   = (const float*)d_in[16];
    const float* var    = (const float*)d_in[17];

    cudaFuncSetAttribute(k_gemm_mma, cudaFuncAttributeMaxDynamicSharedMemorySize,
                         GEMM_SMEM);
    k_gemm_mma<<<dim3(C3_ / 128, HW_ / 128, 4), 256, GEMM_SMEM>>>(
        hsi, lidar, hqkvw, hqkvb, lqkvw, lqkvb);
    k_dwattn<<<dim3(HEADS_ * YT_, B_, 2), 512>>>(hdww, hdwb, ldww, ldwb);
    k_comb  <<<dim3(HEADS_, B_, 2), 64>>>(temp1, temp2);
    k_fuse  <<<dim3(8, B_), 512>>>(projw, projb, gamma, beta, mean, var);
    k_vout  <<<dim3(HEADS_, 4, YT_), 256>>>(hsi, lidar, hdww, hdwb, ldww, ldwb, (float*)d_out);
}

// round 11
// speedup vs baseline: 1.3038x; 1.1935x over previous
#include <cuda_runtime.h>
#include <cuda_fp16.h>
#include <math.h>
#include <cstdint>

#define B_    2
#define C_    512
#define C3_   1536
#define H_    128
#define W_    128
#define HW_   16384
#define HEADS_ 64
#define CH_   8
#define PLANE_ (C3_ * HW_)
#define TENSOR_ ((size_t)B_ * C_ * HW_)
#define YT_   4
#define YROWS_ (H_ / YT_)   // 32

// ---------------- scratch ----------------
__device__ __half g_wh[2][C3_ * C_];          // weights, half, [m][k]
__device__ __half g_xh[4][HW_ * C_];          // inputs, half, TRANSPOSED [n][k]
__device__ __half g_conv[4][PLANE_];          // conv1x1 output, half
__device__ float g_a[2][B_][HEADS_][64];
__device__ float g_pdot[2][B_][HEADS_][YT_][64];
__device__ float g_psq[2][B_][HEADS_][YT_][16];

// ---------------- helpers ----------------
static __device__ __forceinline__ uint32_t s2u(const void* p) {
    uint32_t a;
    asm("{ .reg .u64 t; cvta.to.shared.u64 t, %1; cvt.u32.u64 %0, t; }"
        : "=r"(a) : "l"(p));
    return a;
}
static __device__ __forceinline__ void cpasync16(uint32_t dst, const void* src) {
    asm volatile("cp.async.cg.shared.global [%0], [%1], 16;" :: "r"(dst), "l"(src));
}
static __device__ __forceinline__ void cp_commit() {
    asm volatile("cp.async.commit_group;" ::: "memory");
}
template <int N>
static __device__ __forceinline__ void cp_wait() {
    asm volatile("cp.async.wait_group %0;" :: "n"(N) : "memory");
}
static __device__ __forceinline__ void mma_f16(float& d0, float& d1, float& d2, float& d3,
                                               uint32_t a0, uint32_t a1, uint32_t a2, uint32_t a3,
                                               uint32_t b0, uint32_t b1) {
    asm volatile("mma.sync.aligned.m16n8k16.row.col.f32.f16.f16.f32 "
                 "{%0,%1,%2,%3}, {%4,%5,%6,%7}, {%8,%9}, {%0,%1,%2,%3};"
                 : "+f"(d0), "+f"(d1), "+f"(d2), "+f"(d3)
                 : "r"(a0), "r"(a1), "r"(a2), "r"(a3), "r"(b0), "r"(b1));
}
static __device__ __forceinline__ float4 h4_to_f4(const __half* p) {
    __half2 h0 = *(const __half2*)p;
    __half2 h1 = *(const __half2*)(p + 2);
    float2 f0 = __half22float2(h0), f1 = __half22float2(h1);
    return make_float4(f0.x, f0.y, f1.x, f1.y);
}

// ---------------- K0a: convert weights to half ----
__global__ __launch_bounds__(256) void k_cvtw(
    const float* __restrict__ hw_w, const float* __restrict__ lw_w)
{
    const int mod = blockIdx.y;
    const float* src = mod ? lw_w : hw_w;
    __half* dst = g_wh[mod];
    int i = (blockIdx.x * 256 + threadIdx.x) * 4;
    float4 v = *(const float4*)&src[i];
    __half2 h0 = __floats2half2_rn(v.x, v.y);
    __half2 h1 = __floats2half2_rn(v.z, v.w);
    *(__half2*)&dst[i] = h0;
    *(__half2*)&dst[i + 2] = h1;
}

// ---------------- K0b: transpose-convert X to half [n][k] ----
// grid (HW/32, C/32, 4), block (32,8)
__global__ __launch_bounds__(256) void k_cvtx(
    const float* __restrict__ hsi, const float* __restrict__ lidar)
{
    __shared__ float tile[32][33];
    const int mb = blockIdx.z;
    const int mod = mb >> 1, bb = mb & 1;
    const float* src = (mod ? lidar : hsi) + (size_t)bb * C_ * HW_;
    const int n0 = blockIdx.x * 32;
    const int c0 = blockIdx.y * 32;
    const int tx = threadIdx.x, ty = threadIdx.y;

    #pragma unroll
    for (int r = 0; r < 4; r++) {
        int cc = ty + r * 8;
        tile[cc][tx] = src[(size_t)(c0 + cc) * HW_ + n0 + tx];
    }
    __syncthreads();
    #pragma unroll
    for (int r = 0; r < 4; r++) {
        int nn = ty + r * 8;
        g_xh[mb][(size_t)(n0 + nn) * C_ + c0 + tx] = __float2half(tile[tx][nn]);
    }
}

// ---------------- K1: fp16 mma.sync GEMM (m16n8k16), 3-stage cp.async ----
#define BK_    16
#define KP2_   24                    // halfs per smem row (32B data + 16B pad)
#define ROWB_  48                    // bytes per smem row
#define KITERS (C_ / BK_)            // 32
#define ST_    3
#define TILE_B (128 * ROWB_)         // 6144 B per operand tile
#define GEMM_SMEM (ST_ * 2 * TILE_B) // 36864 B

__global__ __launch_bounds__(256, 2) void k_gemm_mma(
    const float* __restrict__ hw_b, const float* __restrict__ lw_b)
{
    extern __shared__ char smem_g[];
    char* Abase = smem_g;
    char* Bbase = smem_g + ST_ * TILE_B;

    const int tid  = threadIdx.x;
    const int lane = tid & 31;
    const int wid  = tid >> 5;
    const int g    = lane >> 2;
    const int c    = lane & 3;

    const int mb  = blockIdx.z;
    const int mod = mb >> 1;
    const __half* Wm = g_wh[mod];
    const __half* Xt = g_xh[mb];
    const float* bias = mod ? lw_b : hw_b;
    __half* Y = g_conv[mb];
    const int m0 = blockIdx.x * 128;
    const int n0 = blockIdx.y * 128;

    const int warp_m = (wid & 1) * 64;
    const int warp_n = (wid >> 1) * 32;

    const int l_row = tid >> 1;          // 0..127
    const int l_gr  = tid & 1;           // 16B granule (8 halfs)

    const uint32_t asb = s2u(Abase);
    const uint32_t bsb = s2u(Bbase);

    float acc[4][4][4] = {};

    auto load_stage = [&](int s, int k0) {
        cpasync16(asb + s * TILE_B + l_row * ROWB_ + l_gr * 16,
                  &Wm[(size_t)(m0 + l_row) * C_ + k0 + l_gr * 8]);
        cpasync16(bsb + s * TILE_B + l_row * ROWB_ + l_gr * 16,
                  &Xt[(size_t)(n0 + l_row) * C_ + k0 + l_gr * 8]);
    };

    load_stage(0, 0);
    cp_commit();
    load_stage(1, BK_);
    cp_commit();

    for (int it = 0; it < KITERS; it++) {
        const int s = it % ST_;
        cp_wait<1>();
        __syncthreads();

        const char* Ap = Abase + s * TILE_B;
        const char* Bp = Bbase + s * TILE_B;
        uint32_t af[4][4], bf[4][2];
        #pragma unroll
        for (int i = 0; i < 4; i++) {
            int row = warp_m + 16 * i + g;
            af[i][0] = *(const uint32_t*)(Ap + row * ROWB_ + c * 4);
            af[i][1] = *(const uint32_t*)(Ap + (row + 8) * ROWB_ + c * 4);
            af[i][2] = *(const uint32_t*)(Ap + row * ROWB_ + 16 + c * 4);
            af[i][3] = *(const uint32_t*)(Ap + (row + 8) * ROWB_ + 16 + c * 4);
        }
        #pragma unroll
        for (int j = 0; j < 4; j++) {
            int col = warp_n + 8 * j + g;
            bf[j][0] = *(const uint32_t*)(Bp + col * ROWB_ + c * 4);
            bf[j][1] = *(const uint32_t*)(Bp + col * ROWB_ + 16 + c * 4);
        }
        #pragma unroll
        for (int i = 0; i < 4; i++)
            #pragma unroll
            for (int j = 0; j < 4; j++)
                mma_f16(acc[i][j][0], acc[i][j][1], acc[i][j][2], acc[i][j][3],
                        af[i][0], af[i][1], af[i][2], af[i][3],
                        bf[j][0], bf[j][1]);

        const int nxt = it + 2;
        if (nxt < KITERS) load_stage(nxt % ST_, nxt * BK_);
        cp_commit();
    }

    #pragma unroll
    for (int i = 0; i < 4; i++) {
        const int r0 = m0 + warp_m + 16 * i + g;
        const float bi0 = bias[r0];
        const float bi1 = bias[r0 + 8];
        #pragma unroll
        for (int j = 0; j < 4; j++) {
            const int col = n0 + warp_n + 8 * j + 2 * c;
            *(__half2*)&Y[(size_t)r0 * HW_ + col] =
                __floats2half2_rn(acc[i][j][0] + bi0, acc[i][j][1] + bi0);
            *(__half2*)&Y[(size_t)(r0 + 8) * HW_ + col] =
                __floats2half2_rn(acc[i][j][2] + bi1, acc[i][j][3] + bi1);
        }
    }
}

// ---------------- K3: fused dwconv(q,k) + partial ssq + partial channel dot ----
__global__ __launch_bounds__(512) void k_dwattn(
    const float* __restrict__ hdww, const float* __restrict__ hdwb,
    const float* __restrict__ ldww, const float* __restrict__ ldwb)
{
    __shared__ float rowbuf[16][132];
    __shared__ float red[4][16][4];

    const int h = blockIdx.x & 63, yt = blockIdx.x >> 6;
    const int bb = blockIdx.y, a = blockIdx.z;
    const int y0 = yt * YROWS_;
    const int tid = threadIdx.x;
    const int w = tid >> 5, lane = tid & 31;

    const int isk = w >> 3;
    const int ch  = w & 7;
    const int mod = isk ? (1 - a) : a;
    const int plane = (isk ? C_ : 0) + h * CH_ + ch;
    const __half* src = g_conv[mod * 2 + bb] + (size_t)plane * HW_;
    const float* wp  = (mod ? ldww : hdww) + plane * 9;
    float wk[9];
    #pragma unroll
    for (int t = 0; t < 9; t++) wk[t] = __ldg(&wp[t]);
    const float bias = (mod ? ldwb : hdwb)[plane];

    const int x0 = lane * 4;

    float4 pv, cv, nv;
    float pl, pr, cl, cr, nl, nr;
    auto loadrow = [&](int y, float4& v, float& l, float& r) {
        if (y < 0 || y >= H_) { v = make_float4(0.f,0.f,0.f,0.f); l = 0.f; r = 0.f; return; }
        v = h4_to_f4(&src[y * W_ + x0]);
        l = __shfl_up_sync(0xffffffffu, v.w, 1);
        if (lane == 0) l = 0.f;
        r = __shfl_down_sync(0xffffffffu, v.x, 1);
        if (lane == 31) r = 0.f;
    };
    loadrow(y0 - 1, pv, pl, pr);
    loadrow(y0,     cv, cl, cr);
    loadrow(y0 + 1, nv, nl, nr);

    const int xq  = tid & 127;
    const int blk = tid >> 7;
    const int c0  = (blk & 1) * 4;
    const int d0  = (blk >> 1) * 4;

    float ssq = 0.f;
    float acc[4][4] = {};

    for (int y = y0; y < y0 + YROWS_; y++) {
        float o0 = bias
            + wk[0]*pl   + wk[1]*pv.x + wk[2]*pv.y
            + wk[3]*cl   + wk[4]*cv.x + wk[5]*cv.y
            + wk[6]*nl   + wk[7]*nv.x + wk[8]*nv.y;
        float o1 = bias
            + wk[0]*pv.x + wk[1]*pv.y + wk[2]*pv.z
            + wk[3]*cv.x + wk[4]*cv.y + wk[5]*cv.z
            + wk[6]*nv.x + wk[7]*nv.y + wk[8]*nv.z;
        float o2 = bias
            + wk[0]*pv.y + wk[1]*pv.z + wk[2]*pv.w
            + wk[3]*cv.y + wk[4]*cv.z + wk[5]*cv.w
            + wk[6]*nv.y + wk[7]*nv.z + wk[8]*nv.w;
        float o3 = bias
            + wk[0]*pv.z + wk[1]*pv.w + wk[2]*pr
            + wk[3]*cv.z + wk[4]*cv.w + wk[5]*cr
            + wk[6]*nv.z + wk[7]*nv.w + wk[8]*nr;

        __syncthreads();
        *(float4*)&rowbuf[w][x0] = make_float4(o0, o1, o2, o3);
        ssq += o0*o0 + o1*o1 + o2*o2 + o3*o3;

        pv = cv; pl = cl; pr = cr;
        cv = nv; cl = nl; cr = nr;
        loadrow(y + 2, nv, nl, nr);

        __syncthreads();
        float qv[4], kv[4];
        #pragma unroll
        for (int i = 0; i < 4; i++) qv[i] = rowbuf[c0 + i][xq];
        #pragma unroll
        for (int j = 0; j < 4; j++) kv[j] = rowbuf[8 + d0 + j][xq];
        #pragma unroll
        for (int i = 0; i < 4; i++)
            #pragma unroll
            for (int j = 0; j < 4; j++)
                acc[i][j] += qv[i] * kv[j];
    }

    #pragma unroll
    for (int off = 16; off; off >>= 1)
        ssq += __shfl_down_sync(0xffffffffu, ssq, off);
    if (lane == 0) g_psq[a][bb][h][yt][w] = ssq;

    const int wsub = (tid >> 5) & 3;
    #pragma unroll
    for (int i = 0; i < 4; i++)
        #pragma unroll
        for (int j = 0; j < 4; j++) {
            float v = acc[i][j];
            #pragma unroll
            for (int off = 16; off; off >>= 1)
                v += __shfl_down_sync(0xffffffffu, v, off);
            if (lane == 0) red[blk][i * 4 + j][wsub] = v;
        }
    __syncthreads();

    if (tid < 64) {
        int cc = tid >> 3, dd = tid & 7;
        int bq = (cc >> 2) + ((dd >> 2) << 1);
        int ii = cc & 3, jj = dd & 3;
        g_pdot[a][bb][h][yt][tid] =
            red[bq][ii * 4 + jj][0] + red[bq][ii * 4 + jj][1]
          + red[bq][ii * 4 + jj][2] + red[bq][ii * 4 + jj][3];
    }
}

// ---------------- K4: combine partials + score fusion + BN + ReLU + softmax ---------
__global__ __launch_bounds__(512) void k_fuse(
    const float* __restrict__ temp1, const float* __restrict__ temp2,
    const float* __restrict__ projw, const float* __restrict__ projb,
    const float* __restrict__ gamma, const float* __restrict__ beta,
    const float* __restrict__ mean,  const float* __restrict__ var)
{
    __shared__ float attn_s[2][64][64];   // 32 KB
    const int ogrp = blockIdx.x, bb = blockIdx.y;
    const int tid = threadIdx.x;

    for (int e = tid; e < 2 * 64 * 64; e += 512) {
        int aa = e >> 12, hh = (e >> 6) & 63, cd = e & 63;
        int cc = cd >> 3, dd = cd & 7;
        float dot = 0.f, qs = 0.f, ks = 0.f;
        #pragma unroll
        for (int yt = 0; yt < YT_; yt++) {
            dot += g_pdot[aa][bb][hh][yt][cd];
            qs  += g_psq[aa][bb][hh][yt][cc];
            ks  += g_psq[aa][bb][hh][yt][8 + dd];
        }
        float qn = fmaxf(sqrtf(qs), 1e-12f);
        float kn = fmaxf(sqrtf(ks), 1e-12f);
        float tmp = __ldg(&(aa == 0 ? temp1 : temp2)[hh]);
        attn_s[aa][hh][cd] = dot / (qn * kn) * tmp;
    }
    __syncthreads();

    const int o  = ogrp * 8 + (tid >> 6);
    const int cd = tid & 63;
    const float* w = projw + o * 128;
    float s0 = 0.f, s1 = 0.f, s2 = 0.f, s3 = 0.f;
    #pragma unroll 4
    for (int i = 0; i < 64; i += 4) {
        s0 += __ldg(&w[i])     * attn_s[0][i][cd];
        s1 += __ldg(&w[i + 1]) * attn_s[0][i + 1][cd];
        s2 += __ldg(&w[i + 2]) * attn_s[0][i + 2][cd];
        s3 += __ldg(&w[i + 3]) * attn_s[0][i + 3][cd];
    }
    #pragma unroll 4
    for (int i = 0; i < 64; i += 4) {
        s0 += __ldg(&w[64 + i])     * attn_s[1][i][cd];
        s1 += __ldg(&w[64 + i + 1]) * attn_s[1][i + 1][cd];
        s2 += __ldg(&w[64 + i + 2]) * attn_s[1][i + 2][cd];
        s3 += __ldg(&w[64 + i + 3]) * attn_s[1][i + 3][cd];
    }
    float s = __ldg(&projb[o]) + ((s0 + s1) + (s2 + s3));
    s = (s - __ldg(&mean[o])) * rsqrtf(__ldg(&var[o]) + 1e-5f) * __ldg(&gamma[o]) + __ldg(&beta[o]);
    s = fmaxf(s, 0.f);
    #pragma unroll
    for (int a = 0; a < 2; a++) {
        float v = s + attn_s[a][o][cd];
        float m = v;
        #pragma unroll
        for (int off = 4; off; off >>= 1)
            m = fmaxf(m, __shfl_xor_sync(0xffffffffu, m, off, 8));
        float e = expf(v - m);
        float su = e;
        #pragma unroll
        for (int off = 4; off; off >>= 1)
            su += __shfl_xor_sync(0xffffffffu, su, off, 8);
        g_a[a][bb][o][cd] = e / su;
    }
}

// ---------------- K5: fused dwconv(v) + (a @ v + v + x), y-tiled -----------------
__global__ __launch_bounds__(256) void k_vout(
    const float* __restrict__ hsi, const float* __restrict__ lidar,
    const float* __restrict__ hdww, const float* __restrict__ hdwb,
    const float* __restrict__ ldww, const float* __restrict__ ldwb,
    float* __restrict__ out)
{
    __shared__ float rowbuf[8][132];

    const int h = blockIdx.x, mb = blockIdx.y, yt = blockIdx.z;
    const int y0 = yt * YROWS_;
    const int mod = mb >> 1, bb = mb & 1;
    const int tid = threadIdx.x;
    const int w = tid >> 5, lane = tid & 31;

    const int plane = 2 * C_ + h * CH_ + w;
    const __half* src = g_conv[mb] + (size_t)plane * HW_;
    const float* wp  = (mod ? ldww : hdww) + plane * 9;
    float wk[9];
    #pragma unroll
    for (int t = 0; t < 9; t++) wk[t] = __ldg(&wp[t]);
    const float bias = (mod ? ldwb : hdwb)[plane];

    float ar[8];
    #pragma unroll
    for (int d = 0; d < 8; d++) ar[d] = __ldg(&g_a[mod][bb][h][w * 8 + d]);

    const float* xc = (mod ? lidar : hsi) + (size_t)(bb * C_ + h * CH_ + w) * HW_;
    float* oc = out + (size_t)mod * TENSOR_ + (size_t)(bb * C_ + h * CH_ + w) * HW_;

    const int x0 = lane * 4;

    float4 pv, cv, nv;
    float pl, pr, cl, cr, nl, nr;
    auto loadrow = [&](int y, float4& v, float& l, float& r) {
        if (y < 0 || y >= H_) { v = make_float4(0.f,0.f,0.f,0.f); l = 0.f; r = 0.f; return; }
        v = h4_to_f4(&src[y * W_ + x0]);
        l = __shfl_up_sync(0xffffffffu, v.w, 1);
        if (lane == 0) l = 0.f;
        r = __shfl_down_sync(0xffffffffu, v.x, 1);
        if (lane == 31) r = 0.f;
    };
    loadrow(y0 - 1, pv, pl, pr);
    loadrow(y0,     cv, cl, cr);
    loadrow(y0 + 1, nv, nl, nr);

    for (int y = y0; y < y0 + YROWS_; y++) {
        float o0 = bias
            + wk[0]*pl   + wk[1]*pv.x + wk[2]*pv.y
            + wk[3]*cl   + wk[4]*cv.x + wk[5]*cv.y
            + wk[6]*nl   + wk[7]*nv.x + wk[8]*nv.y;
        float o1 = bias
            + wk[0]*pv.x + wk[1]*pv.y + wk[2]*pv.z
            + wk[3]*cv.x + wk[4]*cv.y + wk[5]*cv.z
            + wk[6]*nv.x + wk[7]*nv.y + wk[8]*nv.z;
        float o2 = bias
            + wk[0]*pv.y + wk[1]*pv.z + wk[2]*pv.w
            + wk[3]*cv.y + wk[4]*cv.z + wk[5]*cv.w
            + wk[6]*nv.y + wk[7]*nv.z + wk[8]*nv.w;
        float o3 = bias
            + wk[0]*pv.z + wk[1]*pv.w + wk[2]*pr
            + wk[3]*cv.z + wk[4]*cv.w + wk[5]*cr
            + wk[6]*nv.z + wk[7]*nv.w + wk[8]*nr;

        __syncthreads();
        *(float4*)&rowbuf[w][x0] = make_float4(o0, o1, o2, o3);

        pv = cv; pl = cl; pr = cr;
        cv = nv; cl = nl; cr = nr;
        loadrow(y + 2, nv, nl, nr);

        __syncthreads();
        float4 xin = *(const float4*)&xc[y * W_ + x0];
        float4 s = make_float4(xin.x + o0, xin.y + o1, xin.z + o2, xin.w + o3);
        #pragma unroll
        for (int d = 0; d < 8; d++) {
            float4 vd = *(const float4*)&rowbuf[d][x0];
            s.x += ar[d] * vd.x;
            s.y += ar[d] * vd.y;
            s.z += ar[d] * vd.z;
            s.w += ar[d] * vd.w;
        }
        *(float4*)&oc[y * W_ + x0] = s;
    }
}

// ---------------- launch -----------------------------------------------------------
extern "C" void kernel_launch(void* const* d_in, const int* in_sizes, int n_in,
                              void* d_out, int out_size)
{
    const float* hsi    = (const float*)d_in[0];
    const float* lidar  = (const float*)d_in[1];
    const float* hqkvw  = (const float*)d_in[2];
    const float* hqkvb  = (const float*)d_in[3];
    const float* lqkvw  = (const float*)d_in[4];
    const float* lqkvb  = (const float*)d_in[5];
    const float* hdww   = (const float*)d_in[6];
    const float* hdwb   = (const float*)d_in[7];
    const float* ldww   = (const float*)d_in[8];
    const float* ldwb   = (const float*)d_in[9];
    const float* temp1  = (const float*)d_in[10];
    const float* temp2  = (const float*)d_in[11];
    const float* projw  = (const float*)d_in[12];
    const float* projb  = (const float*)d_in[13];
    const float* gamma  = (const float*)d_in[14];
    const float* beta   = (const float*)d_in[15];
    const float* mean   = (const float*)d_in[16];
    const float* var    = (const float*)d_in[17];

    cudaFuncSetAttribute(k_gemm_mma, cudaFuncAttributeMaxDynamicSharedMemorySize,
                         GEMM_SMEM);

    k_cvtw<<<dim3(C3_ * C_ / 1024, 2), 256>>>(hqkvw, lqkvw);
    k_cvtx<<<dim3(HW_ / 32, C_ / 32, 4), dim3(32, 8)>>>(hsi, lidar);
    k_gemm_mma<<<dim3(C3_ / 128, HW_ / 128, 4), 256, GEMM_SMEM>>>(hqkvb, lqkvb);
    k_dwattn<<<dim3(HEADS_ * YT_, B_, 2), 512>>>(hdww, hdwb, ldww, ldwb);
    k_fuse  <<<dim3(8, B_), 512>>>(temp1, temp2, projw, projb, gamma, beta, mean, var);
    k_vout  <<<dim3(HEADS_, 4, YT_), 256>>>(hsi, lidar, hdww, hdwb, ldww, ldwb, (float*)d_out);
}

// round 13
// speedup vs baseline: 1.3102x; 1.0049x over previous
#include <cuda_runtime.h>
#include <cuda_fp16.h>
#include <math.h>
#include <cstdint>

#define B_    2
#define C_    512
#define C3_   1536
#define H_    128
#define W_    128
#define HW_   16384
#define HEADS_ 64
#define CH_   8
#define PLANE_ (C3_ * HW_)
#define TENSOR_ ((size_t)B_ * C_ * HW_)
#define YT_   4
#define YROWS_ (H_ / YT_)   // 32

// ---------------- scratch ----------------
__device__ __half g_wh[2][C3_ * C_];          // weights, half, [m][k]
__device__ __half g_xh[4][HW_ * C_];          // inputs, half, TRANSPOSED [n][k]
__device__ __half g_conv[4][PLANE_];          // conv1x1 output, half
__device__ float g_a[2][B_][HEADS_][64];
__device__ float g_pdot[2][B_][HEADS_][YT_][64];
__device__ float g_psq[2][B_][HEADS_][YT_][16];

// ---------------- helpers ----------------
static __device__ __forceinline__ uint32_t s2u(const void* p) {
    uint32_t a;
    asm("{ .reg .u64 t; cvta.to.shared.u64 t, %1; cvt.u32.u64 %0, t; }"
        : "=r"(a) : "l"(p));
    return a;
}
static __device__ __forceinline__ void cpasync16(uint32_t dst, const void* src) {
    asm volatile("cp.async.cg.shared.global [%0], [%1], 16;" :: "r"(dst), "l"(src));
}
static __device__ __forceinline__ void cp_commit() {
    asm volatile("cp.async.commit_group;" ::: "memory");
}
template <int N>
static __device__ __forceinline__ void cp_wait() {
    asm volatile("cp.async.wait_group %0;" :: "n"(N) : "memory");
}
static __device__ __forceinline__ void mma_f16(float& d0, float& d1, float& d2, float& d3,
                                               uint32_t a0, uint32_t a1, uint32_t a2, uint32_t a3,
                                               uint32_t b0, uint32_t b1) {
    asm volatile("mma.sync.aligned.m16n8k16.row.col.f32.f16.f16.f32 "
                 "{%0,%1,%2,%3}, {%4,%5,%6,%7}, {%8,%9}, {%0,%1,%2,%3};"
                 : "+f"(d0), "+f"(d1), "+f"(d2), "+f"(d3)
                 : "r"(a0), "r"(a1), "r"(a2), "r"(a3), "r"(b0), "r"(b1));
}
static __device__ __forceinline__ void ldsm_x4(uint32_t& r0, uint32_t& r1,
                                               uint32_t& r2, uint32_t& r3, uint32_t addr) {
    asm volatile("ldmatrix.sync.aligned.m8n8.x4.shared.b16 {%0,%1,%2,%3}, [%4];"
                 : "=r"(r0), "=r"(r1), "=r"(r2), "=r"(r3) : "r"(addr));
}
static __device__ __forceinline__ float4 h4_to_f4(const __half* p) {
    __half2 h0 = *(const __half2*)p;
    __half2 h1 = *(const __half2*)(p + 2);
    float2 f0 = __half22float2(h0), f1 = __half22float2(h1);
    return make_float4(f0.x, f0.y, f1.x, f1.y);
}

// ---------------- K0a: convert weights to half ----
__global__ __launch_bounds__(256) void k_cvtw(
    const float* __restrict__ hw_w, const float* __restrict__ lw_w)
{
    const int mod = blockIdx.y;
    const float* src = mod ? lw_w : hw_w;
    __half* dst = g_wh[mod];
    int i = (blockIdx.x * 256 + threadIdx.x) * 4;
    float4 v = *(const float4*)&src[i];
    *(__half2*)&dst[i]     = __floats2half2_rn(v.x, v.y);
    *(__half2*)&dst[i + 2] = __floats2half2_rn(v.z, v.w);
}

// ---------------- K0b: transpose-convert X to half [n][k] ----
__global__ __launch_bounds__(256) void k_cvtx(
    const float* __restrict__ hsi, const float* __restrict__ lidar)
{
    __shared__ float tile[32][33];
    const int mb = blockIdx.z;
    const int mod = mb >> 1, bb = mb & 1;
    const float* src = (mod ? lidar : hsi) + (size_t)bb * C_ * HW_;
    const int n0 = blockIdx.x * 32;
    const int c0 = blockIdx.y * 32;
    const int tx = threadIdx.x, ty = threadIdx.y;

    #pragma unroll
    for (int r = 0; r < 4; r++) {
        int cc = ty + r * 8;
        tile[cc][tx] = src[(size_t)(c0 + cc) * HW_ + n0 + tx];
    }
    __syncthreads();
    #pragma unroll
    for (int r = 0; r < 4; r++) {
        int nn = ty + r * 8;
        g_xh[mb][(size_t)(n0 + nn) * C_ + c0 + tx] = __float2half(tile[tx][nn]);
    }
}

// ---------------- K1: fp16 mma.sync GEMM (m16n8k16) + ldmatrix, 3-stage cp.async ----
#define BK_    16
#define ROWB_  48                    // bytes per smem row (32B data + 16B pad)
#define KITERS (C_ / BK_)            // 32
#define ST_    3
#define TILE_B (128 * ROWB_)         // 6144 B per operand tile
#define GEMM_SMEM (ST_ * 2 * TILE_B) // 36864 B

__global__ __launch_bounds__(256, 2) void k_gemm_mma(
    const float* __restrict__ hw_b, const float* __restrict__ lw_b)
{
    extern __shared__ char smem_g[];
    char* Abase = smem_g;
    char* Bbase = smem_g + ST_ * TILE_B;

    const int tid  = threadIdx.x;
    const int lane = tid & 31;
    const int wid  = tid >> 5;
    const int g    = lane >> 2;
    const int c    = lane & 3;

    const int mb  = blockIdx.z;
    const int mod = mb >> 1;
    const __half* Wm = g_wh[mod];
    const __half* Xt = g_xh[mb];
    const float* bias = mod ? lw_b : hw_b;
    __half* Y = g_conv[mb];
    const int m0 = blockIdx.x * 128;
    const int n0 = blockIdx.y * 128;

    const int warp_m = (wid & 1) * 64;
    const int warp_n = (wid >> 1) * 32;

    const int l_row = tid >> 1;
    const int l_gr  = tid & 1;

    const uint32_t asb = s2u(Abase);
    const uint32_t bsb = s2u(Bbase);

    // ldmatrix lane addressing
    const int a_r  = lane & 15;            // row within m16 tile
    const int a_ch = (lane >> 4) * 16;     // 16B chunk (k half)
    const int b_r  = lane & 7;             // row within n8 tile
    const int b_q  = lane >> 3;            // 0..3: (j-sub, chunk)
    const int b_js = b_q >> 1;             // 0/1 within pair
    const int b_ch = (b_q & 1) * 16;

    float acc[4][4][4] = {};

    auto load_stage = [&](int s, int k0) {
        cpasync16(asb + s * TILE_B + l_row * ROWB_ + l_gr * 16,
                  &Wm[(size_t)(m0 + l_row) * C_ + k0 + l_gr * 8]);
        cpasync16(bsb + s * TILE_B + l_row * ROWB_ + l_gr * 16,
                  &Xt[(size_t)(n0 + l_row) * C_ + k0 + l_gr * 8]);
    };

    load_stage(0, 0);
    cp_commit();
    load_stage(1, BK_);
    cp_commit();

    for (int it = 0; it < KITERS; it++) {
        const int s = it % ST_;
        cp_wait<1>();
        __syncthreads();

        const uint32_t Ap = asb + s * TILE_B;
        const uint32_t Bp = bsb + s * TILE_B;
        uint32_t af[4][4], bf[4][2];
        #pragma unroll
        for (int i = 0; i < 4; i++)
            ldsm_x4(af[i][0], af[i][1], af[i][2], af[i][3],
                    Ap + (warp_m + 16 * i + a_r) * ROWB_ + a_ch);
        #pragma unroll
        for (int p = 0; p < 2; p++)
            ldsm_x4(bf[2 * p][0], bf[2 * p][1], bf[2 * p + 1][0], bf[2 * p + 1][1],
                    Bp + (warp_n + 8 * (2 * p + b_js) + b_r) * ROWB_ + b_ch);

        #pragma unroll
        for (int i = 0; i < 4; i++)
            #pragma unroll
            for (int j = 0; j < 4; j++)
                mma_f16(acc[i][j][0], acc[i][j][1], acc[i][j][2], acc[i][j][3],
                        af[i][0], af[i][1], af[i][2], af[i][3],
                        bf[j][0], bf[j][1]);

        const int nxt = it + 2;
        if (nxt < KITERS) load_stage(nxt % ST_, nxt * BK_);
        cp_commit();
    }

    #pragma unroll
    for (int i = 0; i < 4; i++) {
        const int r0 = m0 + warp_m + 16 * i + g;
        const float bi0 = bias[r0];
        const float bi1 = bias[r0 + 8];
        #pragma unroll
        for (int j = 0; j < 4; j++) {
            const int col = n0 + warp_n + 8 * j + 2 * c;
            *(__half2*)&Y[(size_t)r0 * HW_ + col] =
                __floats2half2_rn(acc[i][j][0] + bi0, acc[i][j][1] + bi0);
            *(__half2*)&Y[(size_t)(r0 + 8) * HW_ + col] =
                __floats2half2_rn(acc[i][j][2] + bi1, acc[i][j][3] + bi1);
        }
    }
}

// ---------------- depthwise row computation (shared by K3/K5) ----------------
#define DWROW(o0, o1, o2, o3, P, PL, PR, Cv, CL, CR, Nv, NL, NR)                 \
    float o0 = bias + wk[0]*PL + wk[1]*P.x + wk[2]*P.y                           \
             + wk[3]*CL + wk[4]*Cv.x + wk[5]*Cv.y                                \
             + wk[6]*NL + wk[7]*Nv.x + wk[8]*Nv.y;                               \
    float o1 = bias + wk[0]*P.x + wk[1]*P.y + wk[2]*P.z                          \
             + wk[3]*Cv.x + wk[4]*Cv.y + wk[5]*Cv.z                              \
             + wk[6]*Nv.x + wk[7]*Nv.y + wk[8]*Nv.z;                             \
    float o2 = bias + wk[0]*P.y + wk[1]*P.z + wk[2]*P.w                          \
             + wk[3]*Cv.y + wk[4]*Cv.z + wk[5]*Cv.w                              \
             + wk[6]*Nv.y + wk[7]*Nv.z + wk[8]*Nv.w;                             \
    float o3 = bias + wk[0]*P.z + wk[1]*P.w + wk[2]*PR                           \
             + wk[3]*Cv.z + wk[4]*Cv.w + wk[5]*CR                                \
             + wk[6]*Nv.z + wk[7]*Nv.w + wk[8]*NR;

// ---------------- K3: fused dwconv(q,k) + partial ssq + partial dot, 2-row phases ----
__global__ __launch_bounds__(512, 2) void k_dwattn(
    const float* __restrict__ hdww, const float* __restrict__ hdwb,
    const float* __restrict__ ldww, const float* __restrict__ ldwb)
{
    __shared__ float rowbuf[16][2][132];
    __shared__ float red[4][16][4];

    const int h = blockIdx.x & 63, yt = blockIdx.x >> 6;
    const int bb = blockIdx.y, a = blockIdx.z;
    const int y0 = yt * YROWS_;
    const int tid = threadIdx.x;
    const int w = tid >> 5, lane = tid & 31;

    const int isk = w >> 3;
    const int ch  = w & 7;
    const int mod = isk ? (1 - a) : a;
    const int plane = (isk ? C_ : 0) + h * CH_ + ch;
    const __half* src = g_conv[mod * 2 + bb] + (size_t)plane * HW_;
    const float* wp  = (mod ? ldww : hdww) + plane * 9;
    float wk[9];
    #pragma unroll
    for (int t = 0; t < 9; t++) wk[t] = __ldg(&wp[t]);
    const float bias = (mod ? ldwb : hdwb)[plane];

    const int x0 = lane * 4;

    float4 pv, cv, nv, mv;
    float pl, pr, cl, cr, nl, nr, ml, mr;
    auto loadrow = [&](int y, float4& v, float& l, float& r) {
        if (y < 0 || y >= H_) { v = make_float4(0.f,0.f,0.f,0.f); l = 0.f; r = 0.f; return; }
        v = h4_to_f4(&src[y * W_ + x0]);
        l = __shfl_up_sync(0xffffffffu, v.w, 1);
        if (lane == 0) l = 0.f;
        r = __shfl_down_sync(0xffffffffu, v.x, 1);
        if (lane == 31) r = 0.f;
    };
    loadrow(y0 - 1, pv, pl, pr);
    loadrow(y0,     cv, cl, cr);
    loadrow(y0 + 1, nv, nl, nr);
    loadrow(y0 + 2, mv, ml, mr);

    const int xq  = tid & 127;
    const int blk = tid >> 7;
    const int c0  = (blk & 1) * 4;
    const int d0  = (blk >> 1) * 4;

    float ssq = 0.f;
    float acc[4][4] = {};

    for (int y = y0; y < y0 + YROWS_; y += 2) {
        DWROW(o0, o1, o2, o3, pv, pl, pr, cv, cl, cr, nv, nl, nr);
        DWROW(u0, u1, u2, u3, cv, cl, cr, nv, nl, nr, mv, ml, mr);

        __syncthreads();
        *(float4*)&rowbuf[w][0][x0] = make_float4(o0, o1, o2, o3);
        *(float4*)&rowbuf[w][1][x0] = make_float4(u0, u1, u2, u3);
        ssq += o0*o0 + o1*o1 + o2*o2 + o3*o3
             + u0*u0 + u1*u1 + u2*u2 + u3*u3;

        pv = nv; pl = nl; pr = nr;
        cv = mv; cl = ml; cr = mr;
        loadrow(y + 3, nv, nl, nr);
        loadrow(y + 4, mv, ml, mr);

        __syncthreads();
        float qv0[4], kv0[4], qv1[4], kv1[4];
        #pragma unroll
        for (int i = 0; i < 4; i++) {
            qv0[i] = rowbuf[c0 + i][0][xq];
            qv1[i] = rowbuf[c0 + i][1][xq];
        }
        #pragma unroll
        for (int j = 0; j < 4; j++) {
            kv0[j] = rowbuf[8 + d0 + j][0][xq];
            kv1[j] = rowbuf[8 + d0 + j][1][xq];
        }
        #pragma unroll
        for (int i = 0; i < 4; i++)
            #pragma unroll
            for (int j = 0; j < 4; j++)
                acc[i][j] += qv0[i] * kv0[j] + qv1[i] * kv1[j];
    }

    #pragma unroll
    for (int off = 16; off; off >>= 1)
        ssq += __shfl_down_sync(0xffffffffu, ssq, off);
    if (lane == 0) g_psq[a][bb][h][yt][w] = ssq;

    const int wsub = (tid >> 5) & 3;
    #pragma unroll
    for (int i = 0; i < 4; i++)
        #pragma unroll
        for (int j = 0; j < 4; j++) {
            float v = acc[i][j];
            #pragma unroll
            for (int off = 16; off; off >>= 1)
                v += __shfl_down_sync(0xffffffffu, v, off);
            if (lane == 0) red[blk][i * 4 + j][wsub] = v;
        }
    __syncthreads();

    if (tid < 64) {
        int cc = tid >> 3, dd = tid & 7;
        int bq = (cc >> 2) + ((dd >> 2) << 1);
        int ii = cc & 3, jj = dd & 3;
        g_pdot[a][bb][h][yt][tid] =
            red[bq][ii * 4 + jj][0] + red[bq][ii * 4 + jj][1]
          + red[bq][ii * 4 + jj][2] + red[bq][ii * 4 + jj][3];
    }
}

// ---------------- K4: combine partials + score fusion + BN + ReLU + softmax ---------
__global__ __launch_bounds__(512) void k_fuse(
    const float* __restrict__ temp1, const float* __restrict__ temp2,
    const float* __restrict__ projw, const float* __restrict__ projb,
    const float* __restrict__ gamma, const float* __restrict__ beta,
    const float* __restrict__ mean,  const float* __restrict__ var)
{
    __shared__ float attn_s[2][64][64];
    const int ogrp = blockIdx.x, bb = blockIdx.y;
    const int tid = threadIdx.x;

    for (int e = tid; e < 2 * 64 * 64; e += 512) {
        int aa = e >> 12, hh = (e >> 6) & 63, cd = e & 63;
        int cc = cd >> 3, dd = cd & 7;
        float dot = 0.f, qs = 0.f, ks = 0.f;
        #pragma unroll
        for (int yt = 0; yt < YT_; yt++) {
            dot += g_pdot[aa][bb][hh][yt][cd];
            qs  += g_psq[aa][bb][hh][yt][cc];
            ks  += g_psq[aa][bb][hh][yt][8 + dd];
        }
        float qn = fmaxf(sqrtf(qs), 1e-12f);
        float kn = fmaxf(sqrtf(ks), 1e-12f);
        float tmp = __ldg(&(aa == 0 ? temp1 : temp2)[hh]);
        attn_s[aa][hh][cd] = dot / (qn * kn) * tmp;
    }
    __syncthreads();

    const int o  = ogrp * 8 + (tid >> 6);
    const int cd = tid & 63;
    const float* w = projw + o * 128;
    float s0 = 0.f, s1 = 0.f, s2 = 0.f, s3 = 0.f;
    #pragma unroll 4
    for (int i = 0; i < 64; i += 4) {
        s0 += __ldg(&w[i])     * attn_s[0][i][cd];
        s1 += __ldg(&w[i + 1]) * attn_s[0][i + 1][cd];
        s2 += __ldg(&w[i + 2]) * attn_s[0][i + 2][cd];
        s3 += __ldg(&w[i + 3]) * attn_s[0][i + 3][cd];
    }
    #pragma unroll 4
    for (int i = 0; i < 64; i += 4) {
        s0 += __ldg(&w[64 + i])     * attn_s[1][i][cd];
        s1 += __ldg(&w[64 + i + 1]) * attn_s[1][i + 1][cd];
        s2 += __ldg(&w[64 + i + 2]) * attn_s[1][i + 2][cd];
        s3 += __ldg(&w[64 + i + 3]) * attn_s[1][i + 3][cd];
    }
    float s = __ldg(&projb[o]) + ((s0 + s1) + (s2 + s3));
    s = (s - __ldg(&mean[o])) * rsqrtf(__ldg(&var[o]) + 1e-5f) * __ldg(&gamma[o]) + __ldg(&beta[o]);
    s = fmaxf(s, 0.f);
    #pragma unroll
    for (int a = 0; a < 2; a++) {
        float v = s + attn_s[a][o][cd];
        float m = v;
        #pragma unroll
        for (int off = 4; off; off >>= 1)
            m = fmaxf(m, __shfl_xor_sync(0xffffffffu, m, off, 8));
        float e = expf(v - m);
        float su = e;
        #pragma unroll
        for (int off = 4; off; off >>= 1)
            su += __shfl_xor_sync(0xffffffffu, su, off, 8);
        g_a[a][bb][o][cd] = e / su;
    }
}

// ---------------- K5: fused dwconv(v) + (a @ v + v + x), 2-row phases -----------------
__global__ __launch_bounds__(256, 4) void k_vout(
    const float* __restrict__ hsi, const float* __restrict__ lidar,
    const float* __restrict__ hdww, const float* __restrict__ hdwb,
    const float* __restrict__ ldww, const float* __restrict__ ldwb,
    float* __restrict__ out)
{
    __shared__ float rowbuf[8][2][132];

    const int h = blockIdx.x, mb = blockIdx.y, yt = blockIdx.z;
    const int y0 = yt * YROWS_;
    const int mod = mb >> 1, bb = mb & 1;
    const int tid = threadIdx.x;
    const int w = tid >> 5, lane = tid & 31;

    const int plane = 2 * C_ + h * CH_ + w;
    const __half* src = g_conv[mb] + (size_t)plane * HW_;
    const float* wp  = (mod ? ldww : hdww) + plane * 9;
    float wk[9];
    #pragma unroll
    for (int t = 0; t < 9; t++) wk[t] = __ldg(&wp[t]);
    const float bias = (mod ? ldwb : hdwb)[plane];

    float ar[8];
    #pragma unroll
    for (int d = 0; d < 8; d++) ar[d] = __ldg(&g_a[mod][bb][h][w * 8 + d]);

    const float* xc = (mod ? lidar : hsi) + (size_t)(bb * C_ + h * CH_ + w) * HW_;
    float* oc = out + (size_t)mod * TENSOR_ + (size_t)(bb * C_ + h * CH_ + w) * HW_;

    const int x0 = lane * 4;

    float4 pv, cv, nv, mv;
    float pl, pr, cl, cr, nl, nr, ml, mr;
    auto loadrow = [&](int y, float4& v, float& l, float& r) {
        if (y < 0 || y >= H_) { v = make_float4(0.f,0.f,0.f,0.f); l = 0.f; r = 0.f; return; }
        v = h4_to_f4(&src[y * W_ + x0]);
        l = __shfl_up_sync(0xffffffffu, v.w, 1);
        if (lane == 0) l = 0.f;
        r = __shfl_down_sync(0xffffffffu, v.x, 1);
        if (lane == 31) r = 0.f;
    };
    loadrow(y0 - 1, pv, pl, pr);
    loadrow(y0,     cv, cl, cr);
    loadrow(y0 + 1, nv, nl, nr);
    loadrow(y0 + 2, mv, ml, mr);

    for (int y = y0; y < y0 + YROWS_; y += 2) {
        DWROW(o0, o1, o2, o3, pv, pl, pr, cv, cl, cr, nv, nl, nr);
        DWROW(u0, u1, u2, u3, cv, cl, cr, nv, nl, nr, mv, ml, mr);

        __syncthreads();
        *(float4*)&rowbuf[w][0][x0] = make_float4(o0, o1, o2, o3);
        *(float4*)&rowbuf[w][1][x0] = make_float4(u0, u1, u2, u3);

        pv = nv; pl = nl; pr = nr;
        cv = mv; cl = ml; cr = mr;
        loadrow(y + 3, nv, nl, nr);
        loadrow(y + 4, mv, ml, mr);

        __syncthreads();
        float4 xin0 = *(const float4*)&xc[y * W_ + x0];
        float4 xin1 = *(const float4*)&xc[(y + 1) * W_ + x0];
        float4 s0 = make_float4(xin0.x + o0, xin0.y + o1, xin0.z + o2, xin0.w + o3);
        float4 s1 = make_float4(xin1.x + u0, xin1.y + u1, xin1.z + u2, xin1.w + u3);
        #pragma unroll
        for (int d = 0; d < 8; d++) {
            float4 vd0 = *(const float4*)&rowbuf[d][0][x0];
            float4 vd1 = *(const float4*)&rowbuf[d][1][x0];
            s0.x += ar[d] * vd0.x; s0.y += ar[d] * vd0.y;
            s0.z += ar[d] * vd0.z; s0.w += ar[d] * vd0.w;
            s1.x += ar[d] * vd1.x; s1.y += ar[d] * vd1.y;
            s1.z += ar[d] * vd1.z; s1.w += ar[d] * vd1.w;
        }
        *(float4*)&oc[y * W_ + x0] = s0;
        *(float4*)&oc[(y + 1) * W_ + x0] = s1;
    }
}

// ---------------- launch -----------------------------------------------------------
extern "C" void kernel_launch(void* const* d_in, const int* in_sizes, int n_in,
                              void* d_out, int out_size)
{
    const float* hsi    = (const float*)d_in[0];
    const float* lidar  = (const float*)d_in[1];
    const float* hqkvw  = (const float*)d_in[2];
    const float* hqkvb  = (const float*)d_in[3];
    const float* lqkvw  = (const float*)d_in[4];
    const float* lqkvb  = (const float*)d_in[5];
    const float* hdww   = (const float*)d_in[6];
    const float* hdwb   = (const float*)d_in[7];
    const float* ldww   = (const float*)d_in[8];
    const float* ldwb   = (const float*)d_in[9];
    const float* temp1  = (const float*)d_in[10];
    const float* temp2  = (const float*)d_in[11];
    const float* projw  = (const float*)d_in[12];
    const float* projb  = (const float*)d_in[13];
    const float* gamma  = (const float*)d_in[14];
    const float* beta   = (const float*)d_in[15];
    const float* mean   = (const float*)d_in[16];
    const float* var    = (const float*)d_in[17];

    cudaFuncSetAttribute(k_gemm_mma, cudaFuncAttributeMaxDynamicSharedMemorySize,
                         GEMM_SMEM);

    k_cvtw<<<dim3(C3_ * C_ / 1024, 2), 256>>>(hqkvw, lqkvw);
    k_cvtx<<<dim3(HW_ / 32, C_ / 32, 4), dim3(32, 8)>>>(hsi, lidar);
    k_gemm_mma<<<dim3(C3_ / 128, HW_ / 128, 4), 256, GEMM_SMEM>>>(hqkvb, lqkvb);
    k_dwattn<<<dim3(HEADS_ * YT_, B_, 2), 512>>>(hdww, hdwb, ldww, ldwb);
    k_fuse  <<<dim3(8, B_), 512>>>(temp1, temp2, projw, projb, gamma, beta, mean, var);
    k_vout  <<<dim3(HEADS_, 4, YT_), 256>>>(hsi, lidar, hdww, hdwb, ldww, ldwb, (float*)d_out);
}

// round 14
// speedup vs baseline: 1.3809x; 1.0540x over previous
#include <cuda_runtime.h>
#include <cuda_fp16.h>
#include <math.h>
#include <cstdint>

#define B_    2
#define C_    512
#define C3_   1536
#define H_    128
#define W_    128
#define HW_   16384
#define HEADS_ 64
#define CH_   8
#define PLANE_ (C3_ * HW_)
#define TENSOR_ ((size_t)B_ * C_ * HW_)
#define YT_   4
#define YROWS_ (H_ / YT_)   // 32

// ---------------- scratch ----------------
__device__ __half g_wh[2][C3_ * C_];          // weights, half, [m][k]
__device__ __half g_xh[4][HW_ * C_];          // inputs, half, TRANSPOSED [n][k]
__device__ __half g_conv[4][PLANE_];          // conv1x1 output, half
__device__ float g_a[2][B_][HEADS_][64];
__device__ float g_pdot[2][B_][HEADS_][YT_][64];
__device__ float g_psq[2][B_][HEADS_][YT_][16];

// ---------------- helpers ----------------
static __device__ __forceinline__ uint32_t s2u(const void* p) {
    uint32_t a;
    asm("{ .reg .u64 t; cvta.to.shared.u64 t, %1; cvt.u32.u64 %0, t; }"
        : "=r"(a) : "l"(p));
    return a;
}
static __device__ __forceinline__ void cpasync16(uint32_t dst, const void* src) {
    asm volatile("cp.async.cg.shared.global [%0], [%1], 16;" :: "r"(dst), "l"(src));
}
static __device__ __forceinline__ void cp_commit() {
    asm volatile("cp.async.commit_group;" ::: "memory");
}
template <int N>
static __device__ __forceinline__ void cp_wait() {
    asm volatile("cp.async.wait_group %0;" :: "n"(N) : "memory");
}
static __device__ __forceinline__ void mma_f16(float& d0, float& d1, float& d2, float& d3,
                                               uint32_t a0, uint32_t a1, uint32_t a2, uint32_t a3,
                                               uint32_t b0, uint32_t b1) {
    asm volatile("mma.sync.aligned.m16n8k16.row.col.f32.f16.f16.f32 "
                 "{%0,%1,%2,%3}, {%4,%5,%6,%7}, {%8,%9}, {%0,%1,%2,%3};"
                 : "+f"(d0), "+f"(d1), "+f"(d2), "+f"(d3)
                 : "r"(a0), "r"(a1), "r"(a2), "r"(a3), "r"(b0), "r"(b1));
}
static __device__ __forceinline__ void ldsm_x4(uint32_t& r0, uint32_t& r1,
                                               uint32_t& r2, uint32_t& r3, uint32_t addr) {
    asm volatile("ldmatrix.sync.aligned.m8n8.x4.shared.b16 {%0,%1,%2,%3}, [%4];"
                 : "=r"(r0), "=r"(r1), "=r"(r2), "=r"(r3) : "r"(addr));
}
static __device__ __forceinline__ float4 h4_to_f4(const __half* p) {
    __half2 h0 = *(const __half2*)p;
    __half2 h1 = *(const __half2*)(p + 2);
    float2 f0 = __half22float2(h0), f1 = __half22float2(h1);
    return make_float4(f0.x, f0.y, f1.x, f1.y);
}

// ---------------- K0a: convert weights to half ----
__global__ __launch_bounds__(256) void k_cvtw(
    const float* __restrict__ hw_w, const float* __restrict__ lw_w)
{
    const int mod = blockIdx.y;
    const float* src = mod ? lw_w : hw_w;
    __half* dst = g_wh[mod];
    int i = (blockIdx.x * 256 + threadIdx.x) * 4;
    float4 v = *(const float4*)&src[i];
    *(__half2*)&dst[i]     = __floats2half2_rn(v.x, v.y);
    *(__half2*)&dst[i + 2] = __floats2half2_rn(v.z, v.w);
}

// ---------------- K0b: transpose-convert X to half [n][k] ----
__global__ __launch_bounds__(256) void k_cvtx(
    const float* __restrict__ hsi, const float* __restrict__ lidar)
{
    __shared__ float tile[32][33];
    const int mb = blockIdx.z;
    const int mod = mb >> 1, bb = mb & 1;
    const float* src = (mod ? lidar : hsi) + (size_t)bb * C_ * HW_;
    const int n0 = blockIdx.x * 32;
    const int c0 = blockIdx.y * 32;
    const int tx = threadIdx.x, ty = threadIdx.y;

    #pragma unroll
    for (int r = 0; r < 4; r++) {
        int cc = ty + r * 8;
        tile[cc][tx] = src[(size_t)(c0 + cc) * HW_ + n0 + tx];
    }
    __syncthreads();
    #pragma unroll
    for (int r = 0; r < 4; r++) {
        int nn = ty + r * 8;
        g_xh[mb][(size_t)(n0 + nn) * C_ + c0 + tx] = __float2half(tile[tx][nn]);
    }
}

// ---------------- K1: fp16 mma.sync GEMM (m16n8k16) + ldmatrix, 3-stage cp.async ----
#define BK_    16
#define ROWB_  48                    // bytes per smem row (32B data + 16B pad)
#define KITERS (C_ / BK_)            // 32
#define ST_    3
#define TILE_B (128 * ROWB_)         // 6144 B per operand tile
#define GEMM_SMEM (ST_ * 2 * TILE_B) // 36864 B

__global__ __launch_bounds__(256, 2) void k_gemm_mma(
    const float* __restrict__ hw_b, const float* __restrict__ lw_b)
{
    extern __shared__ char smem_g[];
    char* Abase = smem_g;
    char* Bbase = smem_g + ST_ * TILE_B;

    const int tid  = threadIdx.x;
    const int lane = tid & 31;
    const int wid  = tid >> 5;
    const int g    = lane >> 2;
    const int c    = lane & 3;

    const int mb  = blockIdx.z;
    const int mod = mb >> 1;
    const __half* Wm = g_wh[mod];
    const __half* Xt = g_xh[mb];
    const float* bias = mod ? lw_b : hw_b;
    __half* Y = g_conv[mb];
    const int m0 = blockIdx.x * 128;
    const int n0 = blockIdx.y * 128;

    const int warp_m = (wid & 1) * 64;
    const int warp_n = (wid >> 1) * 32;

    const int l_row = tid >> 1;
    const int l_gr  = tid & 1;

    const uint32_t asb = s2u(Abase);
    const uint32_t bsb = s2u(Bbase);

    // ldmatrix lane addressing
    const int a_r  = lane & 15;            // row within m16 tile
    const int a_ch = (lane >> 4) * 16;     // 16B chunk (k half)
    const int b_r  = lane & 7;             // row within n8 tile
    const int b_q  = lane >> 3;            // 0..3
    const int b_js = b_q >> 1;             // 0/1 within pair
    const int b_ch = (b_q & 1) * 16;

    float acc[4][4][4] = {};

    auto load_stage = [&](int s, int k0) {
        cpasync16(asb + s * TILE_B + l_row * ROWB_ + l_gr * 16,
                  &Wm[(size_t)(m0 + l_row) * C_ + k0 + l_gr * 8]);
        cpasync16(bsb + s * TILE_B + l_row * ROWB_ + l_gr * 16,
                  &Xt[(size_t)(n0 + l_row) * C_ + k0 + l_gr * 8]);
    };

    load_stage(0, 0);
    cp_commit();
    load_stage(1, BK_);
    cp_commit();

    for (int it = 0; it < KITERS; it++) {
        const int s = it % ST_;
        cp_wait<1>();
        __syncthreads();

        const uint32_t Ap = asb + s * TILE_B;
        const uint32_t Bp = bsb + s * TILE_B;
        uint32_t af[4][4], bf[4][2];
        #pragma unroll
        for (int i = 0; i < 4; i++)
            ldsm_x4(af[i][0], af[i][1], af[i][2], af[i][3],
                    Ap + (warp_m + 16 * i + a_r) * ROWB_ + a_ch);
        #pragma unroll
        for (int p = 0; p < 2; p++)
            ldsm_x4(bf[2 * p][0], bf[2 * p][1], bf[2 * p + 1][0], bf[2 * p + 1][1],
                    Bp + (warp_n + 8 * (2 * p + b_js) + b_r) * ROWB_ + b_ch);

        #pragma unroll
        for (int i = 0; i < 4; i++)
            #pragma unroll
            for (int j = 0; j < 4; j++)
                mma_f16(acc[i][j][0], acc[i][j][1], acc[i][j][2], acc[i][j][3],
                        af[i][0], af[i][1], af[i][2], af[i][3],
                        bf[j][0], bf[j][1]);

        const int nxt = it + 2;
        if (nxt < KITERS) load_stage(nxt % ST_, nxt * BK_);
        cp_commit();
    }

    #pragma unroll
    for (int i = 0; i < 4; i++) {
        const int r0 = m0 + warp_m + 16 * i + g;
        const float bi0 = bias[r0];
        const float bi1 = bias[r0 + 8];
        #pragma unroll
        for (int j = 0; j < 4; j++) {
            const int col = n0 + warp_n + 8 * j + 2 * c;
            *(__half2*)&Y[(size_t)r0 * HW_ + col] =
                __floats2half2_rn(acc[i][j][0] + bi0, acc[i][j][1] + bi0);
            *(__half2*)&Y[(size_t)(r0 + 8) * HW_ + col] =
                __floats2half2_rn(acc[i][j][2] + bi1, acc[i][j][3] + bi1);
        }
    }
}

// ---------------- K3: fused dwconv(q,k) + partial ssq + partial dot (1-row phases) ----
__global__ __launch_bounds__(512) void k_dwattn(
    const float* __restrict__ hdww, const float* __restrict__ hdwb,
    const float* __restrict__ ldww, const float* __restrict__ ldwb)
{
    __shared__ float rowbuf[16][132];
    __shared__ float red[4][16][4];

    const int h = blockIdx.x & 63, yt = blockIdx.x >> 6;
    const int bb = blockIdx.y, a = blockIdx.z;
    const int y0 = yt * YROWS_;
    const int tid = threadIdx.x;
    const int w = tid >> 5, lane = tid & 31;

    const int isk = w >> 3;
    const int ch  = w & 7;
    const int mod = isk ? (1 - a) : a;
    const int plane = (isk ? C_ : 0) + h * CH_ + ch;
    const __half* src = g_conv[mod * 2 + bb] + (size_t)plane * HW_;
    const float* wp  = (mod ? ldww : hdww) + plane * 9;
    float wk[9];
    #pragma unroll
    for (int t = 0; t < 9; t++) wk[t] = __ldg(&wp[t]);
    const float bias = (mod ? ldwb : hdwb)[plane];

    const int x0 = lane * 4;

    float4 pv, cv, nv;
    float pl, pr, cl, cr, nl, nr;
    auto loadrow = [&](int y, float4& v, float& l, float& r) {
        if (y < 0 || y >= H_) { v = make_float4(0.f,0.f,0.f,0.f); l = 0.f; r = 0.f; return; }
        v = h4_to_f4(&src[y * W_ + x0]);
        l = __shfl_up_sync(0xffffffffu, v.w, 1);
        if (lane == 0) l = 0.f;
        r = __shfl_down_sync(0xffffffffu, v.x, 1);
        if (lane == 31) r = 0.f;
    };
    loadrow(y0 - 1, pv, pl, pr);
    loadrow(y0,     cv, cl, cr);
    loadrow(y0 + 1, nv, nl, nr);

    const int xq  = tid & 127;
    const int blk = tid >> 7;
    const int c0  = (blk & 1) * 4;
    const int d0  = (blk >> 1) * 4;

    float ssq = 0.f;
    float acc[4][4] = {};

    for (int y = y0; y < y0 + YROWS_; y++) {
        float o0 = bias
            + wk[0]*pl   + wk[1]*pv.x + wk[2]*pv.y
            + wk[3]*cl   + wk[4]*cv.x + wk[5]*cv.y
            + wk[6]*nl   + wk[7]*nv.x + wk[8]*nv.y;
        float o1 = bias
            + wk[0]*pv.x + wk[1]*pv.y + wk[2]*pv.z
            + wk[3]*cv.x + wk[4]*cv.y + wk[5]*cv.z
            + wk[6]*nv.x + wk[7]*nv.y + wk[8]*nv.z;
        float o2 = bias
            + wk[0]*pv.y + wk[1]*pv.z + wk[2]*pv.w
            + wk[3]*cv.y + wk[4]*cv.z + wk[5]*cv.w
            + wk[6]*nv.y + wk[7]*nv.z + wk[8]*nv.w;
        float o3 = bias
            + wk[0]*pv.z + wk[1]*pv.w + wk[2]*pr
            + wk[3]*cv.z + wk[4]*cv.w + wk[5]*cr
            + wk[6]*nv.z + wk[7]*nv.w + wk[8]*nr;

        __syncthreads();
        *(float4*)&rowbuf[w][x0] = make_float4(o0, o1, o2, o3);
        ssq += o0*o0 + o1*o1 + o2*o2 + o3*o3;

        pv = cv; pl = cl; pr = cr;
        cv = nv; cl = nl; cr = nr;
        loadrow(y + 2, nv, nl, nr);

        __syncthreads();
        float qv[4], kv[4];
        #pragma unroll
        for (int i = 0; i < 4; i++) qv[i] = rowbuf[c0 + i][xq];
        #pragma unroll
        for (int j = 0; j < 4; j++) kv[j] = rowbuf[8 + d0 + j][xq];
        #pragma unroll
        for (int i = 0; i < 4; i++)
            #pragma unroll
            for (int j = 0; j < 4; j++)
                acc[i][j] += qv[i] * kv[j];
    }

    #pragma unroll
    for (int off = 16; off; off >>= 1)
        ssq += __shfl_down_sync(0xffffffffu, ssq, off);
    if (lane == 0) g_psq[a][bb][h][yt][w] = ssq;

    const int wsub = (tid >> 5) & 3;
    #pragma unroll
    for (int i = 0; i < 4; i++)
        #pragma unroll
        for (int j = 0; j < 4; j++) {
            float v = acc[i][j];
            #pragma unroll
            for (int off = 16; off; off >>= 1)
                v += __shfl_down_sync(0xffffffffu, v, off);
            if (lane == 0) red[blk][i * 4 + j][wsub] = v;
        }
    __syncthreads();

    if (tid < 64) {
        int cc = tid >> 3, dd = tid & 7;
        int bq = (cc >> 2) + ((dd >> 2) << 1);
        int ii = cc & 3, jj = dd & 3;
        g_pdot[a][bb][h][yt][tid] =
            red[bq][ii * 4 + jj][0] + red[bq][ii * 4 + jj][1]
          + red[bq][ii * 4 + jj][2] + red[bq][ii * 4 + jj][3];
    }
}

// ---------------- K4: combine partials + score fusion + BN + ReLU + softmax ---------
__global__ __launch_bounds__(512) void k_fuse(
    const float* __restrict__ temp1, const float* __restrict__ temp2,
    const float* __restrict__ projw, const float* __restrict__ projb,
    const float* __restrict__ gamma, const float* __restrict__ beta,
    const float* __restrict__ mean,  const float* __restrict__ var)
{
    __shared__ float attn_s[2][64][64];
    const int ogrp = blockIdx.x, bb = blockIdx.y;
    const int tid = threadIdx.x;

    for (int e = tid; e < 2 * 64 * 64; e += 512) {
        int aa = e >> 12, hh = (e >> 6) & 63, cd = e & 63;
        int cc = cd >> 3, dd = cd & 7;
        float dot = 0.f, qs = 0.f, ks = 0.f;
        #pragma unroll
        for (int yt = 0; yt < YT_; yt++) {
            dot += g_pdot[aa][bb][hh][yt][cd];
            qs  += g_psq[aa][bb][hh][yt][cc];
            ks  += g_psq[aa][bb][hh][yt][8 + dd];
        }
        float qn = fmaxf(sqrtf(qs), 1e-12f);
        float kn = fmaxf(sqrtf(ks), 1e-12f);
        float tmp = __ldg(&(aa == 0 ? temp1 : temp2)[hh]);
        attn_s[aa][hh][cd] = dot / (qn * kn) * tmp;
    }
    __syncthreads();

    const int o  = ogrp * 8 + (tid >> 6);
    const int cd = tid & 63;
    const float* w = projw + o * 128;
    float s0 = 0.f, s1 = 0.f, s2 = 0.f, s3 = 0.f;
    #pragma unroll 4
    for (int i = 0; i < 64; i += 4) {
        s0 += __ldg(&w[i])     * attn_s[0][i][cd];
        s1 += __ldg(&w[i + 1]) * attn_s[0][i + 1][cd];
        s2 += __ldg(&w[i + 2]) * attn_s[0][i + 2][cd];
        s3 += __ldg(&w[i + 3]) * attn_s[0][i + 3][cd];
    }
    #pragma unroll 4
    for (int i = 0; i < 64; i += 4) {
        s0 += __ldg(&w[64 + i])     * attn_s[1][i][cd];
        s1 += __ldg(&w[64 + i + 1]) * attn_s[1][i + 1][cd];
        s2 += __ldg(&w[64 + i + 2]) * attn_s[1][i + 2][cd];
        s3 += __ldg(&w[64 + i + 3]) * attn_s[1][i + 3][cd];
    }
    float s = __ldg(&projb[o]) + ((s0 + s1) + (s2 + s3));
    s = (s - __ldg(&mean[o])) * rsqrtf(__ldg(&var[o]) + 1e-5f) * __ldg(&gamma[o]) + __ldg(&beta[o]);
    s = fmaxf(s, 0.f);
    #pragma unroll
    for (int a = 0; a < 2; a++) {
        float v = s + attn_s[a][o][cd];
        float m = v;
        #pragma unroll
        for (int off = 4; off; off >>= 1)
            m = fmaxf(m, __shfl_xor_sync(0xffffffffu, m, off, 8));
        float e = expf(v - m);
        float su = e;
        #pragma unroll
        for (int off = 4; off; off >>= 1)
            su += __shfl_xor_sync(0xffffffffu, su, off, 8);
        g_a[a][bb][o][cd] = e / su;
    }
}

// ---------------- K5: fused dwconv(v) + (a @ v + v + x), 1-row phases -----------------
__global__ __launch_bounds__(256) void k_vout(
    const float* __restrict__ hsi, const float* __restrict__ lidar,
    const float* __restrict__ hdww, const float* __restrict__ hdwb,
    const float* __restrict__ ldww, const float* __restrict__ ldwb,
    float* __restrict__ out)
{
    __shared__ float rowbuf[8][132];

    const int h = blockIdx.x, mb = blockIdx.y, yt = blockIdx.z;
    const int y0 = yt * YROWS_;
    const int mod = mb >> 1, bb = mb & 1;
    const int tid = threadIdx.x;
    const int w = tid >> 5, lane = tid & 31;

    const int plane = 2 * C_ + h * CH_ + w;
    const __half* src = g_conv[mb] + (size_t)plane * HW_;
    const float* wp  = (mod ? ldww : hdww) + plane * 9;
    float wk[9];
    #pragma unroll
    for (int t = 0; t < 9; t++) wk[t] = __ldg(&wp[t]);
    const float bias = (mod ? ldwb : hdwb)[plane];

    float ar[8];
    #pragma unroll
    for (int d = 0; d < 8; d++) ar[d] = __ldg(&g_a[mod][bb][h][w * 8 + d]);

    const float* xc = (mod ? lidar : hsi) + (size_t)(bb * C_ + h * CH_ + w) * HW_;
    float* oc = out + (size_t)mod * TENSOR_ + (size_t)(bb * C_ + h * CH_ + w) * HW_;

    const int x0 = lane * 4;

    float4 pv, cv, nv;
    float pl, pr, cl, cr, nl, nr;
    auto loadrow = [&](int y, float4& v, float& l, float& r) {
        if (y < 0 || y >= H_) { v = make_float4(0.f,0.f,0.f,0.f); l = 0.f; r = 0.f; return; }
        v = h4_to_f4(&src[y * W_ + x0]);
        l = __shfl_up_sync(0xffffffffu, v.w, 1);
        if (lane == 0) l = 0.f;
        r = __shfl_down_sync(0xffffffffu, v.x, 1);
        if (lane == 31) r = 0.f;
    };
    loadrow(y0 - 1, pv, pl, pr);
    loadrow(y0,     cv, cl, cr);
    loadrow(y0 + 1, nv, nl, nr);

    for (int y = y0; y < y0 + YROWS_; y++) {
        float o0 = bias
            + wk[0]*pl   + wk[1]*pv.x + wk[2]*pv.y
            + wk[3]*cl   + wk[4]*cv.x + wk[5]*cv.y
            + wk[6]*nl   + wk[7]*nv.x + wk[8]*nv.y;
        float o1 = bias
            + wk[0]*pv.x + wk[1]*pv.y + wk[2]*pv.z
            + wk[3]*cv.x + wk[4]*cv.y + wk[5]*cv.z
            + wk[6]*nv.x + wk[7]*nv.y + wk[8]*nv.z;
        float o2 = bias
            + wk[0]*pv.y + wk[1]*pv.z + wk[2]*pv.w
            + wk[3]*cv.y + wk[4]*cv.z + wk[5]*cv.w
            + wk[6]*nv.y + wk[7]*nv.z + wk[8]*nv.w;
        float o3 = bias
            + wk[0]*pv.z + wk[1]*pv.w + wk[2]*pr
            + wk[3]*cv.z + wk[4]*cv.w + wk[5]*cr
            + wk[6]*nv.z + wk[7]*nv.w + wk[8]*nr;

        __syncthreads();
        *(float4*)&rowbuf[w][x0] = make_float4(o0, o1, o2, o3);

        pv = cv; pl = cl; pr = cr;
        cv = nv; cl = nl; cr = nr;
        loadrow(y + 2, nv, nl, nr);

        __syncthreads();
        float4 xin = *(const float4*)&xc[y * W_ + x0];
        float4 s = make_float4(xin.x + o0, xin.y + o1, xin.z + o2, xin.w + o3);
        #pragma unroll
        for (int d = 0; d < 8; d++) {
            float4 vd = *(const float4*)&rowbuf[d][x0];
            s.x += ar[d] * vd.x;
            s.y += ar[d] * vd.y;
            s.z += ar[d] * vd.z;
            s.w += ar[d] * vd.w;
        }
        *(float4*)&oc[y * W_ + x0] = s;
    }
}

// ---------------- launch -----------------------------------------------------------
extern "C" void kernel_launch(void* const* d_in, const int* in_sizes, int n_in,
                              void* d_out, int out_size)
{
    const float* hsi    = (const float*)d_in[0];
    const float* lidar  = (const float*)d_in[1];
    const float* hqkvw  = (const float*)d_in[2];
    const float* hqkvb  = (const float*)d_in[3];
    const float* lqkvw  = (const float*)d_in[4];
    const float* lqkvb  = (const float*)d_in[5];
    const float* hdww   = (const float*)d_in[6];
    const float* hdwb   = (const float*)d_in[7];
    const float* ldww   = (const float*)d_in[8];
    const float* ldwb   = (const float*)d_in[9];
    const float* temp1  = (const float*)d_in[10];
    const float* temp2  = (const float*)d_in[11];
    const float* projw  = (const float*)d_in[12];
    const float* projb  = (const float*)d_in[13];
    const float* gamma  = (const float*)d_in[14];
    const float* beta   = (const float*)d_in[15];
    const float* mean   = (const float*)d_in[16];
    const float* var    = (const float*)d_in[17];

    cudaFuncSetAttribute(k_gemm_mma, cudaFuncAttributeMaxDynamicSharedMemorySize,
                         GEMM_SMEM);

    k_cvtw<<<dim3(C3_ * C_ / 1024, 2), 256>>>(hqkvw, lqkvw);
    k_cvtx<<<dim3(HW_ / 32, C_ / 32, 4), dim3(32, 8)>>>(hsi, lidar);
    k_gemm_mma<<<dim3(C3_ / 128, HW_ / 128, 4), 256, GEMM_SMEM>>>(hqkvb, lqkvb);
    k_dwattn<<<dim3(HEADS_ * YT_, B_, 2), 512>>>(hdww, hdwb, ldww, ldwb);
    k_fuse  <<<dim3(8, B_), 512>>>(temp1, temp2, projw, projb, gamma, beta, mean, var);
    k_vout  <<<dim3(HEADS_, 4, YT_), 256>>>(hsi, lidar, hdww, hdwb, ldww, ldwb, (float*)d_out);
}

// round 15
// speedup vs baseline: 1.5913x; 1.1523x over previous
#include <cuda_runtime.h>
#include <cuda_fp16.h>
#include <math.h>
#include <cstdint>

#define B_    2
#define C_    512
#define C3_   1536
#define H_    128
#define W_    128
#define HW_   16384
#define HEADS_ 64
#define CH_   8
#define PLANE_ (C3_ * HW_)
#define TENSOR_ ((size_t)B_ * C_ * HW_)
#define YT_   4
#define YROWS_ (H_ / YT_)   // 32

// ---------------- scratch ----------------
__device__ __half g_wh[2][C3_ * C_];          // weights, half, [m][k]
__device__ __half g_xh[4][HW_ * C_];          // inputs, half, TRANSPOSED [n][k]
__device__ __half g_conv[4][PLANE_];          // conv1x1 output, half
__device__ float g_a[2][B_][HEADS_][64];
__device__ float g_pdot[2][B_][HEADS_][YT_][64];
__device__ float g_psq[2][B_][HEADS_][YT_][16];

// ---------------- helpers ----------------
static __device__ __forceinline__ uint32_t s2u(const void* p) {
    uint32_t a;
    asm("{ .reg .u64 t; cvta.to.shared.u64 t, %1; cvt.u32.u64 %0, t; }"
        : "=r"(a) : "l"(p));
    return a;
}
static __device__ __forceinline__ void cpasync16(uint32_t dst, const void* src) {
    asm volatile("cp.async.cg.shared.global [%0], [%1], 16;" :: "r"(dst), "l"(src));
}
static __device__ __forceinline__ void cp_commit() {
    asm volatile("cp.async.commit_group;" ::: "memory");
}
template <int N>
static __device__ __forceinline__ void cp_wait() {
    asm volatile("cp.async.wait_group %0;" :: "n"(N) : "memory");
}
static __device__ __forceinline__ void mma_f16(float& d0, float& d1, float& d2, float& d3,
                                               uint32_t a0, uint32_t a1, uint32_t a2, uint32_t a3,
                                               uint32_t b0, uint32_t b1) {
    asm volatile("mma.sync.aligned.m16n8k16.row.col.f32.f16.f16.f32 "
                 "{%0,%1,%2,%3}, {%4,%5,%6,%7}, {%8,%9}, {%0,%1,%2,%3};"
                 : "+f"(d0), "+f"(d1), "+f"(d2), "+f"(d3)
                 : "r"(a0), "r"(a1), "r"(a2), "r"(a3), "r"(b0), "r"(b1));
}
static __device__ __forceinline__ void ldsm_x4(uint32_t& r0, uint32_t& r1,
                                               uint32_t& r2, uint32_t& r3, uint32_t addr) {
    asm volatile("ldmatrix.sync.aligned.m8n8.x4.shared.b16 {%0,%1,%2,%3}, [%4];"
                 : "=r"(r0), "=r"(r1), "=r"(r2), "=r"(r3) : "r"(addr));
}
static __device__ __forceinline__ float4 h4_to_f4(const __half* p) {
    __half2 h0 = *(const __half2*)p;
    __half2 h1 = *(const __half2*)(p + 2);
    float2 f0 = __half22float2(h0), f1 = __half22float2(h1);
    return make_float4(f0.x, f0.y, f1.x, f1.y);
}

// ---------------- K0a: convert weights to half ----
__global__ __launch_bounds__(256) void k_cvtw(
    const float* __restrict__ hw_w, const float* __restrict__ lw_w)
{
    const int mod = blockIdx.y;
    const float* src = mod ? lw_w : hw_w;
    __half* dst = g_wh[mod];
    int i = (blockIdx.x * 256 + threadIdx.x) * 4;
    float4 v = *(const float4*)&src[i];
    *(__half2*)&dst[i]     = __floats2half2_rn(v.x, v.y);
    *(__half2*)&dst[i + 2] = __floats2half2_rn(v.z, v.w);
}

// ---------------- K0b: transpose-convert X to half [n][k] ----
__global__ __launch_bounds__(256) void k_cvtx(
    const float* __restrict__ hsi, const float* __restrict__ lidar)
{
    __shared__ float tile[32][33];
    const int mb = blockIdx.z;
    const int mod = mb >> 1, bb = mb & 1;
    const float* src = (mod ? lidar : hsi) + (size_t)bb * C_ * HW_;
    const int n0 = blockIdx.x * 32;
    const int c0 = blockIdx.y * 32;
    const int tx = threadIdx.x, ty = threadIdx.y;

    #pragma unroll
    for (int r = 0; r < 4; r++) {
        int cc = ty + r * 8;
        tile[cc][tx] = src[(size_t)(c0 + cc) * HW_ + n0 + tx];
    }
    __syncthreads();
    #pragma unroll
    for (int r = 0; r < 4; r++) {
        int nn = ty + r * 8;
        g_xh[mb][(size_t)(n0 + nn) * C_ + c0 + tx] = __float2half(tile[tx][nn]);
    }
}

// ---------------- K1: fp16 mma.sync GEMM (m16n8k16) + ldmatrix, BK=32, 3-stage ----
#define BK_    32
#define ROWB_  80                    // bytes per smem row (64B data + 16B pad)
#define KITERS (C_ / BK_)            // 16
#define ST_    3
#define TILE_B (128 * ROWB_)         // 10240 B per operand tile
#define GEMM_SMEM (ST_ * 2 * TILE_B) // 61440 B

__global__ __launch_bounds__(256, 2) void k_gemm_mma(
    const float* __restrict__ hw_b, const float* __restrict__ lw_b)
{
    extern __shared__ char smem_g[];
    char* Abase = smem_g;
    char* Bbase = smem_g + ST_ * TILE_B;

    const int tid  = threadIdx.x;
    const int lane = tid & 31;
    const int wid  = tid >> 5;
    const int g    = lane >> 2;
    const int c    = lane & 3;

    const int mb  = blockIdx.z;
    const int mod = mb >> 1;
    const __half* Wm = g_wh[mod];
    const __half* Xt = g_xh[mb];
    const float* bias = mod ? lw_b : hw_b;
    __half* Y = g_conv[mb];
    const int m0 = blockIdx.x * 128;
    const int n0 = blockIdx.y * 128;

    const int warp_m = (wid & 1) * 64;
    const int warp_n = (wid >> 1) * 32;

    const uint32_t asb = s2u(Abase);
    const uint32_t bsb = s2u(Bbase);

    // ldmatrix lane addressing
    const int a_r  = lane & 15;            // row within m16 tile
    const int a_ch = (lane >> 4) * 16;     // 16B chunk within k16 group
    const int b_r  = lane & 7;             // row within n8 tile
    const int b_q  = lane >> 3;            // 0..3
    const int b_js = b_q >> 1;             // 0/1 within pair
    const int b_ch = (b_q & 1) * 16;

    float acc[4][4][4] = {};

    auto load_stage = [&](int s, int k0) {
        #pragma unroll
        for (int i = 0; i < 2; i++) {
            int idx = tid + 256 * i;
            int row = idx >> 2;
            int gr  = idx & 3;
            cpasync16(asb + s * TILE_B + row * ROWB_ + gr * 16,
                      &Wm[(size_t)(m0 + row) * C_ + k0 + gr * 8]);
            cpasync16(bsb + s * TILE_B + row * ROWB_ + gr * 16,
                      &Xt[(size_t)(n0 + row) * C_ + k0 + gr * 8]);
        }
    };

    load_stage(0, 0);
    cp_commit();
    load_stage(1, BK_);
    cp_commit();

    for (int it = 0; it < KITERS; it++) {
        const int s = it % ST_;
        cp_wait<1>();
        __syncthreads();

        const uint32_t Ap = asb + s * TILE_B;
        const uint32_t Bp = bsb + s * TILE_B;
        #pragma unroll
        for (int kk = 0; kk < 2; kk++) {
            const int ko = kk * 32;   // byte offset of k16 group
            uint32_t af[4][4], bf[4][2];
            #pragma unroll
            for (int i = 0; i < 4; i++)
                ldsm_x4(af[i][0], af[i][1], af[i][2], af[i][3],
                        Ap + (warp_m + 16 * i + a_r) * ROWB_ + ko + a_ch);
            #pragma unroll
            for (int p = 0; p < 2; p++)
                ldsm_x4(bf[2 * p][0], bf[2 * p][1], bf[2 * p + 1][0], bf[2 * p + 1][1],
                        Bp + (warp_n + 8 * (2 * p + b_js) + b_r) * ROWB_ + ko + b_ch);

            #pragma unroll
            for (int i = 0; i < 4; i++)
                #pragma unroll
                for (int j = 0; j < 4; j++)
                    mma_f16(acc[i][j][0], acc[i][j][1], acc[i][j][2], acc[i][j][3],
                            af[i][0], af[i][1], af[i][2], af[i][3],
                            bf[j][0], bf[j][1]);
        }

        const int nxt = it + 2;
        if (nxt < KITERS) load_stage(nxt % ST_, nxt * BK_);
        cp_commit();
    }

    #pragma unroll
    for (int i = 0; i < 4; i++) {
        const int r0 = m0 + warp_m + 16 * i + g;
        const float bi0 = bias[r0];
        const float bi1 = bias[r0 + 8];
        #pragma unroll
        for (int j = 0; j < 4; j++) {
            const int col = n0 + warp_n + 8 * j + 2 * c;
            *(__half2*)&Y[(size_t)r0 * HW_ + col] =
                __floats2half2_rn(acc[i][j][0] + bi0, acc[i][j][1] + bi0);
            *(__half2*)&Y[(size_t)(r0 + 8) * HW_ + col] =
                __floats2half2_rn(acc[i][j][2] + bi1, acc[i][j][3] + bi1);
        }
    }
}

// ---------------- K3: fused dwconv(q,k) + partials, double-buffered, 1 barrier/row ----
__global__ __launch_bounds__(512) void k_dwattn(
    const float* __restrict__ hdww, const float* __restrict__ hdwb,
    const float* __restrict__ ldww, const float* __restrict__ ldwb)
{
    __shared__ float rowbuf[16][2][132];
    __shared__ float red[4][16][4];

    const int h = blockIdx.x & 63, yt = blockIdx.x >> 6;
    const int bb = blockIdx.y, a = blockIdx.z;
    const int y0 = yt * YROWS_;
    const int tid = threadIdx.x;
    const int w = tid >> 5, lane = tid & 31;

    const int isk = w >> 3;
    const int ch  = w & 7;
    const int mod = isk ? (1 - a) : a;
    const int plane = (isk ? C_ : 0) + h * CH_ + ch;
    const __half* src = g_conv[mod * 2 + bb] + (size_t)plane * HW_;
    const float* wp  = (mod ? ldww : hdww) + plane * 9;
    float wk[9];
    #pragma unroll
    for (int t = 0; t < 9; t++) wk[t] = __ldg(&wp[t]);
    const float bias = (mod ? ldwb : hdwb)[plane];

    const int x0 = lane * 4;

    float4 pv, cv, nv;
    float pl, pr, cl, cr, nl, nr;
    auto loadrow = [&](int y, float4& v, float& l, float& r) {
        if (y < 0 || y >= H_) { v = make_float4(0.f,0.f,0.f,0.f); l = 0.f; r = 0.f; return; }
        v = h4_to_f4(&src[y * W_ + x0]);
        l = __shfl_up_sync(0xffffffffu, v.w, 1);
        if (lane == 0) l = 0.f;
        r = __shfl_down_sync(0xffffffffu, v.x, 1);
        if (lane == 31) r = 0.f;
    };
    loadrow(y0 - 1, pv, pl, pr);
    loadrow(y0,     cv, cl, cr);
    loadrow(y0 + 1, nv, nl, nr);

    const int xq  = tid & 127;
    const int blk = tid >> 7;
    const int c0  = (blk & 1) * 4;
    const int d0  = (blk >> 1) * 4;

    float ssq = 0.f;
    float acc[4][4] = {};

    for (int y = y0; y < y0 + YROWS_; y++) {
        const int slot = y & 1;
        float o0 = bias
            + wk[0]*pl   + wk[1]*pv.x + wk[2]*pv.y
            + wk[3]*cl   + wk[4]*cv.x + wk[5]*cv.y
            + wk[6]*nl   + wk[7]*nv.x + wk[8]*nv.y;
        float o1 = bias
            + wk[0]*pv.x + wk[1]*pv.y + wk[2]*pv.z
            + wk[3]*cv.x + wk[4]*cv.y + wk[5]*cv.z
            + wk[6]*nv.x + wk[7]*nv.y + wk[8]*nv.z;
        float o2 = bias
            + wk[0]*pv.y + wk[1]*pv.z + wk[2]*pv.w
            + wk[3]*cv.y + wk[4]*cv.z + wk[5]*cv.w
            + wk[6]*nv.y + wk[7]*nv.z + wk[8]*nv.w;
        float o3 = bias
            + wk[0]*pv.z + wk[1]*pv.w + wk[2]*pr
            + wk[3]*cv.z + wk[4]*cv.w + wk[5]*cr
            + wk[6]*nv.z + wk[7]*nv.w + wk[8]*nr;

        *(float4*)&rowbuf[w][slot][x0] = make_float4(o0, o1, o2, o3);
        ssq += o0*o0 + o1*o1 + o2*o2 + o3*o3;

        __syncthreads();   // writes of row y visible; prior slot reads all complete

        pv = cv; pl = cl; pr = cr;
        cv = nv; cl = nl; cr = nr;
        loadrow(y + 2, nv, nl, nr);   // gmem prefetch overlaps dot phase

        float qv[4], kv[4];
        #pragma unroll
        for (int i = 0; i < 4; i++) qv[i] = rowbuf[c0 + i][slot][xq];
        #pragma unroll
        for (int j = 0; j < 4; j++) kv[j] = rowbuf[8 + d0 + j][slot][xq];
        #pragma unroll
        for (int i = 0; i < 4; i++)
            #pragma unroll
            for (int j = 0; j < 4; j++)
                acc[i][j] += qv[i] * kv[j];
    }

    #pragma unroll
    for (int off = 16; off; off >>= 1)
        ssq += __shfl_down_sync(0xffffffffu, ssq, off);
    if (lane == 0) g_psq[a][bb][h][yt][w] = ssq;

    const int wsub = (tid >> 5) & 3;
    #pragma unroll
    for (int i = 0; i < 4; i++)
        #pragma unroll
        for (int j = 0; j < 4; j++) {
            float v = acc[i][j];
            #pragma unroll
            for (int off = 16; off; off >>= 1)
                v += __shfl_down_sync(0xffffffffu, v, off);
            if (lane == 0) red[blk][i * 4 + j][wsub] = v;
        }
    __syncthreads();

    if (tid < 64) {
        int cc = tid >> 3, dd = tid & 7;
        int bq = (cc >> 2) + ((dd >> 2) << 1);
        int ii = cc & 3, jj = dd & 3;
        g_pdot[a][bb][h][yt][tid] =
            red[bq][ii * 4 + jj][0] + red[bq][ii * 4 + jj][1]
          + red[bq][ii * 4 + jj][2] + red[bq][ii * 4 + jj][3];
    }
}

// ---------------- K4: combine partials + score fusion + BN + ReLU + softmax ---------
__global__ __launch_bounds__(512) void k_fuse(
    const float* __restrict__ temp1, const float* __restrict__ temp2,
    const float* __restrict__ projw, const float* __restrict__ projb,
    const float* __restrict__ gamma, const float* __restrict__ beta,
    const float* __restrict__ mean,  const float* __restrict__ var)
{
    __shared__ float attn_s[2][64][64];
    const int ogrp = blockIdx.x, bb = blockIdx.y;
    const int tid = threadIdx.x;

    for (int e = tid; e < 2 * 64 * 64; e += 512) {
        int aa = e >> 12, hh = (e >> 6) & 63, cd = e & 63;
        int cc = cd >> 3, dd = cd & 7;
        float dot = 0.f, qs = 0.f, ks = 0.f;
        #pragma unroll
        for (int yt = 0; yt < YT_; yt++) {
            dot += g_pdot[aa][bb][hh][yt][cd];
            qs  += g_psq[aa][bb][hh][yt][cc];
            ks  += g_psq[aa][bb][hh][yt][8 + dd];
        }
        float qn = fmaxf(sqrtf(qs), 1e-12f);
        float kn = fmaxf(sqrtf(ks), 1e-12f);
        float tmp = __ldg(&(aa == 0 ? temp1 : temp2)[hh]);
        attn_s[aa][hh][cd] = dot / (qn * kn) * tmp;
    }
    __syncthreads();

    const int o  = ogrp * 8 + (tid >> 6);
    const int cd = tid & 63;
    const float* w = projw + o * 128;
    float s0 = 0.f, s1 = 0.f, s2 = 0.f, s3 = 0.f;
    #pragma unroll 4
    for (int i = 0; i < 64; i += 4) {
        s0 += __ldg(&w[i])     * attn_s[0][i][cd];
        s1 += __ldg(&w[i + 1]) * attn_s[0][i + 1][cd];
        s2 += __ldg(&w[i + 2]) * attn_s[0][i + 2][cd];
        s3 += __ldg(&w[i + 3]) * attn_s[0][i + 3][cd];
    }
    #pragma unroll 4
    for (int i = 0; i < 64; i += 4) {
        s0 += __ldg(&w[64 + i])     * attn_s[1][i][cd];
        s1 += __ldg(&w[64 + i + 1]) * attn_s[1][i + 1][cd];
        s2 += __ldg(&w[64 + i + 2]) * attn_s[1][i + 2][cd];
        s3 += __ldg(&w[64 + i + 3]) * attn_s[1][i + 3][cd];
    }
    float s = __ldg(&projb[o]) + ((s0 + s1) + (s2 + s3));
    s = (s - __ldg(&mean[o])) * rsqrtf(__ldg(&var[o]) + 1e-5f) * __ldg(&gamma[o]) + __ldg(&beta[o]);
    s = fmaxf(s, 0.f);
    #pragma unroll
    for (int a = 0; a < 2; a++) {
        float v = s + attn_s[a][o][cd];
        float m = v;
        #pragma unroll
        for (int off = 4; off; off >>= 1)
            m = fmaxf(m, __shfl_xor_sync(0xffffffffu, m, off, 8));
        float e = expf(v - m);
        float su = e;
        #pragma unroll
        for (int off = 4; off; off >>= 1)
            su += __shfl_xor_sync(0xffffffffu, su, off, 8);
        g_a[a][bb][o][cd] = e / su;
    }
}

// ---------------- K5: fused dwconv(v) + (a @ v + v + x), double-buffered ----------
__global__ __launch_bounds__(256) void k_vout(
    const float* __restrict__ hsi, const float* __restrict__ lidar,
    const float* __restrict__ hdww, const float* __restrict__ hdwb,
    const float* __restrict__ ldww, const float* __restrict__ ldwb,
    float* __restrict__ out)
{
    __shared__ float rowbuf[8][2][132];

    const int h = blockIdx.x, mb = blockIdx.y, yt = blockIdx.z;
    const int y0 = yt * YROWS_;
    const int mod = mb >> 1, bb = mb & 1;
    const int tid = threadIdx.x;
    const int w = tid >> 5, lane = tid & 31;

    const int plane = 2 * C_ + h * CH_ + w;
    const __half* src = g_conv[mb] + (size_t)plane * HW_;
    const float* wp  = (mod ? ldww : hdww) + plane * 9;
    float wk[9];
    #pragma unroll
    for (int t = 0; t < 9; t++) wk[t] = __ldg(&wp[t]);
    const float bias = (mod ? ldwb : hdwb)[plane];

    float ar[8];
    #pragma unroll
    for (int d = 0; d < 8; d++) ar[d] = __ldg(&g_a[mod][bb][h][w * 8 + d]);

    const float* xc = (mod ? lidar : hsi) + (size_t)(bb * C_ + h * CH_ + w) * HW_;
    float* oc = out + (size_t)mod * TENSOR_ + (size_t)(bb * C_ + h * CH_ + w) * HW_;

    const int x0 = lane * 4;

    float4 pv, cv, nv;
    float pl, pr, cl, cr, nl, nr;
    auto loadrow = [&](int y, float4& v, float& l, float& r) {
        if (y < 0 || y >= H_) { v = make_float4(0.f,0.f,0.f,0.f); l = 0.f; r = 0.f; return; }
        v = h4_to_f4(&src[y * W_ + x0]);
        l = __shfl_up_sync(0xffffffffu, v.w, 1);
        if (lane == 0) l = 0.f;
        r = __shfl_down_sync(0xffffffffu, v.x, 1);
        if (lane == 31) r = 0.f;
    };
    loadrow(y0 - 1, pv, pl, pr);
    loadrow(y0,     cv, cl, cr);
    loadrow(y0 + 1, nv, nl, nr);

    for (int y = y0; y < y0 + YROWS_; y++) {
        const int slot = y & 1;
        float o0 = bias
            + wk[0]*pl   + wk[1]*pv.x + wk[2]*pv.y
            + wk[3]*cl   + wk[4]*cv.x + wk[5]*cv.y
            + wk[6]*nl   + wk[7]*nv.x + wk[8]*nv.y;
        float o1 = bias
            + wk[0]*pv.x + wk[1]*pv.y + wk[2]*pv.z
            + wk[3]*cv.x + wk[4]*cv.y + wk[5]*cv.z
            + wk[6]*nv.x + wk[7]*nv.y + wk[8]*nv.z;
        float o2 = bias
            + wk[0]*pv.y + wk[1]*pv.z + wk[2]*pv.w
            + wk[3]*cv.y + wk[4]*cv.z + wk[5]*cv.w
            + wk[6]*nv.y + wk[7]*nv.z + wk[8]*nv.w;
        float o3 = bias
            + wk[0]*pv.z + wk[1]*pv.w + wk[2]*pr
            + wk[3]*cv.z + wk[4]*cv.w + wk[5]*cr
            + wk[6]*nv.z + wk[7]*nv.w + wk[8]*nr;

        *(float4*)&rowbuf[w][slot][x0] = make_float4(o0, o1, o2, o3);

        __syncthreads();

        pv = cv; pl = cl; pr = cr;
        cv = nv; cl = nl; cr = nr;
        loadrow(y + 2, nv, nl, nr);

        float4 xin = *(const float4*)&xc[y * W_ + x0];
        float4 s = make_float4(xin.x + o0, xin.y + o1, xin.z + o2, xin.w + o3);
        #pragma unroll
        for (int d = 0; d < 8; d++) {
            float4 vd = *(const float4*)&rowbuf[d][slot][x0];
            s.x += ar[d] * vd.x;
            s.y += ar[d] * vd.y;
            s.z += ar[d] * vd.z;
            s.w += ar[d] * vd.w;
        }
        *(float4*)&oc[y * W_ + x0] = s;
    }
}

// ---------------- launch -----------------------------------------------------------
extern "C" void kernel_launch(void* const* d_in, const int* in_sizes, int n_in,
                              void* d_out, int out_size)
{
    const float* hsi    = (const float*)d_in[0];
    const float* lidar  = (const float*)d_in[1];
    const float* hqkvw  = (const float*)d_in[2];
    const float* hqkvb  = (const float*)d_in[3];
    const float* lqkvw  = (const float*)d_in[4];
    const float* lqkvb  = (const float*)d_in[5];
    const float* hdww   = (const float*)d_in[6];
    const float* hdwb   = (const float*)d_in[7];
    const float* ldww   = (const float*)d_in[8];
    const float* ldwb   = (const float*)d_in[9];
    const float* temp1  = (const float*)d_in[10];
    const float* temp2  = (const float*)d_in[11];
    const float* projw  = (const float*)d_in[12];
    const float* projb  = (const float*)d_in[13];
    const float* gamma  = (const float*)d_in[14];
    const float* beta   = (const float*)d_in[15];
    const float* mean   = (const float*)d_in[16];
    const float* var    = (const float*)d_in[17];

    cudaFuncSetAttribute(k_gemm_mma, cudaFuncAttributeMaxDynamicSharedMemorySize,
                         GEMM_SMEM);

    k_cvtw<<<dim3(C3_ * C_ / 1024, 2), 256>>>(hqkvw, lqkvw);
    k_cvtx<<<dim3(HW_ / 32, C_ / 32, 4), dim3(32, 8)>>>(hsi, lidar);
    k_gemm_mma<<<dim3(C3_ / 128, HW_ / 128, 4), 256, GEMM_SMEM>>>(hqkvb, lqkvb);
    k_dwattn<<<dim3(HEADS_ * YT_, B_, 2), 512>>>(hdww, hdwb, ldww, ldwb);
    k_fuse  <<<dim3(8, B_), 512>>>(temp1, temp2, projw, projb, gamma, beta, mean, var);
    k_vout  <<<dim3(HEADS_, 4, YT_), 256>>>(hsi, lidar, hdww, hdwb, ldww, ldwb, (float*)d_out);
}